// round 2
// baseline (speedup 1.0000x reference)
#include <cuda_runtime.h>
#include <cstdint>
#include <cstddef>

// Problem constants
#define BB 4
#define NN 2048
#define CC 768
#define HH 12
#define DD 64

// Scratch (allocation-free rule: __device__ globals)
__device__ float g_Q[(size_t)BB * HH * NN * DD];   // pre-scaled by D^-0.5
__device__ float g_K[(size_t)BB * HH * NN * DD];
__device__ float g_V[(size_t)BB * HH * NN * DD];
__device__ float g_O[(size_t)BB * NN * CC];        // [B,N,C] attention output

// ---------------------------------------------------------------------------
// SGEMM: C[M,Nw] = A[M,K] @ W[K,Nw] + bias  (128x128 tile, BK=8, 256 thr, 8x8)
// MODE 0: epilogue scatters into g_Q/g_K/g_V ([B,H,N,D], Q scaled 0.125)
// MODE 1: A is g_O, epilogue writes Cout[row*Nw+col]
// ---------------------------------------------------------------------------
template <int MODE>
__global__ __launch_bounds__(256) void sgemm_kernel(
    const float* __restrict__ A, const float* __restrict__ W,
    const float* __restrict__ bias, float* __restrict__ Cout,
    int K, int Nw)
{
    __shared__ float As[8][128];
    __shared__ float Bs[8][128];

    const float* Ap = (MODE == 1) ? (const float*)g_O : A;

    int tid  = threadIdx.x;
    int brow = blockIdx.y;   // M tile
    int bcol = blockIdx.x;   // N tile

    const float* Ablk = Ap + (size_t)brow * 128 * K;
    const float* Wblk = W + (size_t)bcol * 128;

    int arow  = tid >> 1;            // 0..127
    int acol  = (tid & 1) << 2;      // 0 or 4
    int brw   = tid >> 5;            // 0..7
    int bcl   = (tid & 31) << 2;     // 0..124

    int tr = (tid >> 4) << 3;        // 0..120 step 8
    int tc = (tid & 15) << 3;        // 0..120 step 8

    float acc[8][8];
    #pragma unroll
    for (int i = 0; i < 8; i++)
        #pragma unroll
        for (int j = 0; j < 8; j++) acc[i][j] = 0.f;

    for (int k0 = 0; k0 < K; k0 += 8) {
        float4 av = *(const float4*)(Ablk + (size_t)arow * K + k0 + acol);
        As[acol + 0][arow] = av.x;
        As[acol + 1][arow] = av.y;
        As[acol + 2][arow] = av.z;
        As[acol + 3][arow] = av.w;
        *(float4*)&Bs[brw][bcl] =
            *(const float4*)(Wblk + (size_t)(k0 + brw) * Nw + bcl);
        __syncthreads();

        #pragma unroll
        for (int k = 0; k < 8; k++) {
            float ra[8], rb[8];
            *(float4*)(ra)     = *(const float4*)&As[k][tr];
            *(float4*)(ra + 4) = *(const float4*)&As[k][tr + 4];
            *(float4*)(rb)     = *(const float4*)&Bs[k][tc];
            *(float4*)(rb + 4) = *(const float4*)&Bs[k][tc + 4];
            #pragma unroll
            for (int i = 0; i < 8; i++)
                #pragma unroll
                for (int j = 0; j < 8; j++)
                    acc[i][j] += ra[i] * rb[j];
        }
        __syncthreads();
    }

    #pragma unroll
    for (int i = 0; i < 8; i++) {
        int row = brow * 128 + tr + i;
        #pragma unroll
        for (int j = 0; j < 8; j++) {
            int col = bcol * 128 + tc + j;
            float v = acc[i][j] + bias[col];
            if (MODE == 0) {
                int t   = col / CC;            // 0=q 1=k 2=v
                int rem = col - t * CC;
                int h   = rem >> 6;
                int d   = rem & 63;
                int b   = row >> 11;
                int n   = row & 2047;
                size_t idx = (((size_t)b * HH + h) * NN + n) * DD + d;
                if (t == 0)      g_Q[idx] = v * 0.125f;   // D^-0.5
                else if (t == 1) g_K[idx] = v;
                else             g_V[idx] = v;
            } else {
                Cout[(size_t)row * Nw + col] = v;
            }
        }
    }
}

// ---------------------------------------------------------------------------
// Flash attention: per CTA one (b,h) x 64-query tile; key tiles of 32.
// 256 threads = 8 warps; warp owns 8 query rows; lane owns key-col = lane.
// Online softmax, alibi added, padding mask -> -1e30. O written in [B,N,C].
// ---------------------------------------------------------------------------
__global__ __launch_bounds__(256) void attn_kernel(
    const float* __restrict__ alibi, const int* __restrict__ mask)
{
    __shared__ float Qs[64][64];   // broadcast-only reads: no padding needed
    __shared__ float Ks[32][65];   // padded: (lane*65+k)%32 = (lane+k)%32
    __shared__ float Vs[32][65];
    __shared__ float Ps[64][33];

    int b = blockIdx.z, h = blockIdx.y;
    int q0 = blockIdx.x * 64;
    int tid = threadIdx.x, warp = tid >> 5, lane = tid & 31;

    size_t bh = (size_t)b * HH + h;
    const float* Qg = g_Q + (bh * NN + q0) * DD;
    const float* Kg = g_K + bh * NN * DD;
    const float* Vg = g_V + bh * NN * DD;
    const float* alibi_bh = alibi + (bh * NN + q0) * (size_t)NN;
    const int* mask_b = mask + (size_t)b * NN;

    // Load Q tile (64x64)
    for (int i = tid; i < 64 * 16; i += 256) {
        int r = i >> 4, c4 = (i & 15) << 2;
        *(float4*)&Qs[r][c4] = *(const float4*)(Qg + (size_t)r * DD + c4);
    }

    float mi[8], li[8], acc0[8], acc1[8];
    #pragma unroll
    for (int i = 0; i < 8; i++) { mi[i] = -1e30f; li[i] = 0.f; acc0[i] = 0.f; acc1[i] = 0.f; }

    int row0 = warp * 8;

    for (int kt = 0; kt < NN / 32; kt++) {
        __syncthreads();                       // previous tile fully consumed
        int m0 = kt * 32;
        for (int i = tid; i < 32 * 16; i += 256) {
            int r = i >> 4, c4 = (i & 15) << 2;
            float4 kv = *(const float4*)(Kg + (size_t)(m0 + r) * DD + c4);
            Ks[r][c4] = kv.x; Ks[r][c4 + 1] = kv.y; Ks[r][c4 + 2] = kv.z; Ks[r][c4 + 3] = kv.w;
            float4 vv = *(const float4*)(Vg + (size_t)(m0 + r) * DD + c4);
            Vs[r][c4] = vv.x; Vs[r][c4 + 1] = vv.y; Vs[r][c4 + 2] = vv.z; Vs[r][c4 + 3] = vv.w;
        }
        __syncthreads();

        // Scores: 8 rows x (this lane's key column)
        float sv[8];
        #pragma unroll
        for (int i = 0; i < 8; i++) sv[i] = 0.f;
        #pragma unroll
        for (int k = 0; k < 64; k += 4) {
            float k0v = Ks[lane][k], k1v = Ks[lane][k + 1];
            float k2v = Ks[lane][k + 2], k3v = Ks[lane][k + 3];
            #pragma unroll
            for (int ri = 0; ri < 8; ri++) {
                float4 q = *(const float4*)&Qs[row0 + ri][k];
                sv[ri] += q.x * k0v + q.y * k1v + q.z * k2v + q.w * k3v;
            }
        }

        bool msk = mask_b[m0 + lane] != 0;

        #pragma unroll
        for (int ri = 0; ri < 8; ri++) {
            int row = row0 + ri;
            float s = sv[ri] + alibi_bh[(size_t)row * NN + m0 + lane];
            if (msk) s = -1e30f;
            float tm = s;
            #pragma unroll
            for (int o = 16; o > 0; o >>= 1)
                tm = fmaxf(tm, __shfl_xor_sync(0xffffffffu, tm, o));
            float mnew = fmaxf(mi[ri], tm);
            float p = __expf(s - mnew);
            float ps = p;
            #pragma unroll
            for (int o = 16; o > 0; o >>= 1)
                ps += __shfl_xor_sync(0xffffffffu, ps, o);
            float alpha = __expf(mi[ri] - mnew);
            li[ri] = li[ri] * alpha + ps;
            mi[ri] = mnew;
            acc0[ri] *= alpha;
            acc1[ri] *= alpha;
            Ps[row][lane] = p;
        }
        __syncwarp();

        // O accumulation: acc[row][d] += sum_m P[row][m] * V[m][d]
        #pragma unroll 8
        for (int m = 0; m < 32; m++) {
            float v0 = Vs[m][lane];
            float v1 = Vs[m][lane + 32];
            #pragma unroll
            for (int ri = 0; ri < 8; ri++) {
                float pv = Ps[row0 + ri][m];
                acc0[ri] += pv * v0;
                acc1[ri] += pv * v1;
            }
        }
        // next-iteration __syncthreads() protects Ps/Ks/Vs reuse
    }

    #pragma unroll
    for (int ri = 0; ri < 8; ri++) {
        int grow = q0 + row0 + ri;
        float invl = 1.0f / li[ri];
        size_t base = ((size_t)b * NN + grow) * CC + h * DD;
        g_O[base + lane]      = acc0[ri] * invl;
        g_O[base + lane + 32] = acc1[ri] * invl;
    }
}

// ---------------------------------------------------------------------------
extern "C" void kernel_launch(void* const* d_in, const int* in_sizes, int n_in,
                              void* d_out, int out_size)
{
    const float* x      = (const float*)d_in[0];
    const int*   pmask  = (const int*)d_in[1];    // jnp.bool_ canonicalized to int32
    const float* alibi  = (const float*)d_in[2];
    const float* qkv_w  = (const float*)d_in[3];
    const float* qkv_b  = (const float*)d_in[4];
    const float* proj_w = (const float*)d_in[5];
    const float* proj_b = (const float*)d_in[6];
    float*       out    = (float*)d_out;

    // 1) QKV projection (M=8192, K=768, N=2304) with scatter epilogue
    sgemm_kernel<0><<<dim3(2304 / 128, (BB * NN) / 128), 256>>>(
        x, qkv_w, qkv_b, nullptr, CC, 3 * CC);

    // 2) Flash attention with alibi + padding mask
    attn_kernel<<<dim3(NN / 64, HH, BB), 256>>>(alibi, pmask);

    // 3) Output projection (M=8192, K=768, N=768)
    sgemm_kernel<1><<<dim3(CC / 128, (BB * NN) / 128), 256>>>(
        nullptr, proj_w, proj_b, out, CC, CC);
}

// round 4
// speedup vs baseline: 1.6562x; 1.6562x over previous
#include <cuda_runtime.h>
#include <cstdint>
#include <cstddef>

// Problem constants
#define BB 4
#define NN 2048
#define CC 768
#define HH 12
#define DD 64

// Scratch (allocation-free rule: __device__ globals)
__device__ float g_Q[(size_t)BB * HH * NN * DD];   // pre-scaled by D^-0.5
__device__ float g_K[(size_t)BB * HH * NN * DD];
__device__ float g_V[(size_t)BB * HH * NN * DD];
__device__ float g_O[(size_t)BB * NN * CC];        // [B,N,C] attention output

// ---------------------------------------------------------------------------
// SGEMM (unchanged from passing round): 128x128 tile, BK=8, 256 thr, 8x8
// ---------------------------------------------------------------------------
template <int MODE>
__global__ __launch_bounds__(256) void sgemm_kernel(
    const float* __restrict__ A, const float* __restrict__ W,
    const float* __restrict__ bias, float* __restrict__ Cout,
    int K, int Nw)
{
    __shared__ float As[8][128];
    __shared__ float Bs[8][128];

    const float* Ap = (MODE == 1) ? (const float*)g_O : A;

    int tid  = threadIdx.x;
    int brow = blockIdx.y;
    int bcol = blockIdx.x;

    const float* Ablk = Ap + (size_t)brow * 128 * K;
    const float* Wblk = W + (size_t)bcol * 128;

    int arow  = tid >> 1;
    int acol  = (tid & 1) << 2;
    int brw   = tid >> 5;
    int bcl   = (tid & 31) << 2;

    int tr = (tid >> 4) << 3;
    int tc = (tid & 15) << 3;

    float acc[8][8];
    #pragma unroll
    for (int i = 0; i < 8; i++)
        #pragma unroll
        for (int j = 0; j < 8; j++) acc[i][j] = 0.f;

    for (int k0 = 0; k0 < K; k0 += 8) {
        float4 av = *(const float4*)(Ablk + (size_t)arow * K + k0 + acol);
        As[acol + 0][arow] = av.x;
        As[acol + 1][arow] = av.y;
        As[acol + 2][arow] = av.z;
        As[acol + 3][arow] = av.w;
        *(float4*)&Bs[brw][bcl] =
            *(const float4*)(Wblk + (size_t)(k0 + brw) * Nw + bcl);
        __syncthreads();

        #pragma unroll
        for (int k = 0; k < 8; k++) {
            float ra[8], rb[8];
            *(float4*)(ra)     = *(const float4*)&As[k][tr];
            *(float4*)(ra + 4) = *(const float4*)&As[k][tr + 4];
            *(float4*)(rb)     = *(const float4*)&Bs[k][tc];
            *(float4*)(rb + 4) = *(const float4*)&Bs[k][tc + 4];
            #pragma unroll
            for (int i = 0; i < 8; i++)
                #pragma unroll
                for (int j = 0; j < 8; j++)
                    acc[i][j] += ra[i] * rb[j];
        }
        __syncthreads();
    }

    #pragma unroll
    for (int i = 0; i < 8; i++) {
        int row = brow * 128 + tr + i;
        #pragma unroll
        for (int j = 0; j < 8; j++) {
            int col = bcol * 128 + tc + j;
            float v = acc[i][j] + bias[col];
            if (MODE == 0) {
                int t   = col / CC;
                int rem = col - t * CC;
                int h   = rem >> 6;
                int d   = rem & 63;
                int b   = row >> 11;
                int n   = row & 2047;
                size_t idx = (((size_t)b * HH + h) * NN + n) * DD + d;
                if (t == 0)      g_Q[idx] = v * 0.125f;
                else if (t == 1) g_K[idx] = v;
                else             g_V[idx] = v;
            } else {
                Cout[(size_t)row * Nw + col] = v;
            }
        }
    }
}

// ---------------------------------------------------------------------------
// tf32 helpers
// ---------------------------------------------------------------------------
__device__ __forceinline__ uint32_t f2tf(float x) {
    uint32_t r;
    asm("cvt.rna.tf32.f32 %0, %1;" : "=r"(r) : "f"(x));
    return r;
}

__device__ __forceinline__ void mma_tf32(float c[4], const uint32_t a[4],
                                         const uint32_t b[2]) {
    asm volatile(
        "mma.sync.aligned.m16n8k8.row.col.f32.tf32.tf32.f32 "
        "{%0,%1,%2,%3}, {%4,%5,%6,%7}, {%8,%9}, {%0,%1,%2,%3};\n"
        : "+f"(c[0]), "+f"(c[1]), "+f"(c[2]), "+f"(c[3])
        : "r"(a[0]), "r"(a[1]), "r"(a[2]), "r"(a[3]),
          "r"(b[0]), "r"(b[1]));
}

// ---------------------------------------------------------------------------
// Flash attention on tensor pipe (mma.sync m16n8k8 tf32).
// CTA: 128 thr = 4 warps; warp owns 16 query rows; BM=64, BN=64 keys/tile.
// Smem strides: Qs/Ks/Ps 68 (bank pattern 4g+tg: conflict-free),
//               Vs 72 (bank pattern 8tg+g: conflict-free).
// ---------------------------------------------------------------------------
__global__ __launch_bounds__(128) void attn_mma_kernel(
    const float* __restrict__ alibi, const int* __restrict__ mask)
{
    extern __shared__ uint32_t smem[];
    uint32_t* Qs = smem;                        // [64][68] tf32
    uint32_t* Ks = smem + 64 * 68;              // [64][68] tf32
    uint32_t* Vs = smem + 2 * 64 * 68;          // [64][72] tf32
    uint32_t* Ps = smem + 2 * 64 * 68 + 64 * 72;// [64][68] tf32

    const int b = blockIdx.z, h = blockIdx.y;
    const int q0 = blockIdx.x * 64;
    const int tid = threadIdx.x;
    const int warp = tid >> 5, lane = tid & 31;
    const int g = lane >> 2, tg = lane & 3;     // groupID, threadInGroup
    const int m0w = warp * 16;

    size_t bh = (size_t)b * HH + h;
    const float* Qg = g_Q + (bh * NN + q0) * DD;
    const float* Kg = g_K + bh * NN * DD;
    const float* Vg = g_V + bh * NN * DD;
    const float* alibi_bh = alibi + (bh * NN + q0) * (size_t)NN;
    const int* mask_b = mask + (size_t)b * NN;

    // Load + convert Q tile (64x64)
    for (int i = tid; i < 64 * 16; i += 128) {
        int r = i >> 4, c4 = (i & 15) << 2;
        float4 q = *(const float4*)(Qg + (size_t)r * DD + c4);
        Qs[r * 68 + c4 + 0] = f2tf(q.x);
        Qs[r * 68 + c4 + 1] = f2tf(q.y);
        Qs[r * 68 + c4 + 2] = f2tf(q.z);
        Qs[r * 68 + c4 + 3] = f2tf(q.w);
    }

    float oacc[8][4];
    #pragma unroll
    for (int nb = 0; nb < 8; nb++)
        #pragma unroll
        for (int c = 0; c < 4; c++) oacc[nb][c] = 0.f;

    float mi0 = -1e30f, mi1 = -1e30f, li0 = 0.f, li1 = 0.f;

    for (int kt = 0; kt < NN / 64; kt++) {
        const int m0 = kt * 64;
        __syncthreads();   // prior tile consumed (and Q visible on first iter)
        for (int i = tid; i < 64 * 16; i += 128) {
            int r = i >> 4, c4 = (i & 15) << 2;
            float4 kv = *(const float4*)(Kg + (size_t)(m0 + r) * DD + c4);
            Ks[r * 68 + c4 + 0] = f2tf(kv.x);
            Ks[r * 68 + c4 + 1] = f2tf(kv.y);
            Ks[r * 68 + c4 + 2] = f2tf(kv.z);
            Ks[r * 68 + c4 + 3] = f2tf(kv.w);
            float4 vv = *(const float4*)(Vg + (size_t)(m0 + r) * DD + c4);
            Vs[r * 72 + c4 + 0] = f2tf(vv.x);
            Vs[r * 72 + c4 + 1] = f2tf(vv.y);
            Vs[r * 72 + c4 + 2] = f2tf(vv.z);
            Vs[r * 72 + c4 + 3] = f2tf(vv.w);
        }
        __syncthreads();

        // --- S = Q K^T on tensor pipe ---
        float sacc[8][4];
        #pragma unroll
        for (int nb = 0; nb < 8; nb++)
            #pragma unroll
            for (int c = 0; c < 4; c++) sacc[nb][c] = 0.f;

        #pragma unroll
        for (int kk = 0; kk < 8; kk++) {
            const int ak = kk * 8;
            uint32_t a[4];
            a[0] = Qs[(m0w + g)     * 68 + ak + tg];
            a[1] = Qs[(m0w + g + 8) * 68 + ak + tg];
            a[2] = Qs[(m0w + g)     * 68 + ak + tg + 4];
            a[3] = Qs[(m0w + g + 8) * 68 + ak + tg + 4];
            #pragma unroll
            for (int nb = 0; nb < 8; nb++) {
                uint32_t bf[2];
                bf[0] = Ks[(nb * 8 + g) * 68 + ak + tg];
                bf[1] = Ks[(nb * 8 + g) * 68 + ak + tg + 4];
                mma_tf32(sacc[nb], a, bf);
            }
        }

        // --- alibi + mask, tile max ---
        float tm0 = -1e30f, tm1 = -1e30f;
        #pragma unroll
        for (int nb = 0; nb < 8; nb++) {
            int col = m0 + nb * 8 + 2 * tg;
            float2 al0 = *(const float2*)(alibi_bh + (size_t)(m0w + g) * NN + col);
            float2 al1 = *(const float2*)(alibi_bh + (size_t)(m0w + g + 8) * NN + col);
            int2 mk = *(const int2*)(mask_b + col);
            sacc[nb][0] = mk.x ? -1e30f : sacc[nb][0] + al0.x;
            sacc[nb][1] = mk.y ? -1e30f : sacc[nb][1] + al0.y;
            sacc[nb][2] = mk.x ? -1e30f : sacc[nb][2] + al1.x;
            sacc[nb][3] = mk.y ? -1e30f : sacc[nb][3] + al1.y;
            tm0 = fmaxf(tm0, fmaxf(sacc[nb][0], sacc[nb][1]));
            tm1 = fmaxf(tm1, fmaxf(sacc[nb][2], sacc[nb][3]));
        }
        tm0 = fmaxf(tm0, __shfl_xor_sync(0xffffffffu, tm0, 1));
        tm0 = fmaxf(tm0, __shfl_xor_sync(0xffffffffu, tm0, 2));
        tm1 = fmaxf(tm1, __shfl_xor_sync(0xffffffffu, tm1, 1));
        tm1 = fmaxf(tm1, __shfl_xor_sync(0xffffffffu, tm1, 2));

        // --- online softmax ---
        float mn0 = fmaxf(mi0, tm0), mn1 = fmaxf(mi1, tm1);
        float a0 = __expf(mi0 - mn0), a1 = __expf(mi1 - mn1);
        float sum0 = 0.f, sum1 = 0.f;
        #pragma unroll
        for (int nb = 0; nb < 8; nb++) {
            float p00 = __expf(sacc[nb][0] - mn0);
            float p01 = __expf(sacc[nb][1] - mn0);
            float p10 = __expf(sacc[nb][2] - mn1);
            float p11 = __expf(sacc[nb][3] - mn1);
            sum0 += p00 + p01;
            sum1 += p10 + p11;
            uint2 w0; w0.x = f2tf(p00); w0.y = f2tf(p01);
            *(uint2*)&Ps[(m0w + g) * 68 + nb * 8 + 2 * tg] = w0;
            uint2 w1; w1.x = f2tf(p10); w1.y = f2tf(p11);
            *(uint2*)&Ps[(m0w + g + 8) * 68 + nb * 8 + 2 * tg] = w1;
            oacc[nb][0] *= a0; oacc[nb][1] *= a0;
            oacc[nb][2] *= a1; oacc[nb][3] *= a1;
        }
        sum0 += __shfl_xor_sync(0xffffffffu, sum0, 1);
        sum0 += __shfl_xor_sync(0xffffffffu, sum0, 2);
        sum1 += __shfl_xor_sync(0xffffffffu, sum1, 1);
        sum1 += __shfl_xor_sync(0xffffffffu, sum1, 2);
        li0 = li0 * a0 + sum0;
        li1 = li1 * a1 + sum1;
        mi0 = mn0; mi1 = mn1;
        __syncwarp();   // P visible to own warp's A-frag loads

        // --- O += P V on tensor pipe ---
        #pragma unroll
        for (int kk = 0; kk < 8; kk++) {
            const int kp = kk * 8;
            uint32_t a[4];
            a[0] = Ps[(m0w + g)     * 68 + kp + tg];
            a[1] = Ps[(m0w + g + 8) * 68 + kp + tg];
            a[2] = Ps[(m0w + g)     * 68 + kp + tg + 4];
            a[3] = Ps[(m0w + g + 8) * 68 + kp + tg + 4];
            #pragma unroll
            for (int nb = 0; nb < 8; nb++) {
                uint32_t bf[2];
                bf[0] = Vs[(kp + tg)     * 72 + nb * 8 + g];
                bf[1] = Vs[(kp + tg + 4) * 72 + nb * 8 + g];
                mma_tf32(oacc[nb], a, bf);
            }
        }
    }

    // Epilogue: normalize, write [B,N,C]
    float inv0 = 1.f / li0, inv1 = 1.f / li1;
    float* O0 = g_O + ((size_t)b * NN + q0 + m0w + g) * CC + h * DD;
    float* O1 = O0 + 8 * (size_t)CC;
    #pragma unroll
    for (int nb = 0; nb < 8; nb++) {
        float2 o0; o0.x = oacc[nb][0] * inv0; o0.y = oacc[nb][1] * inv0;
        *(float2*)(O0 + nb * 8 + 2 * tg) = o0;
        float2 o1; o1.x = oacc[nb][2] * inv1; o1.y = oacc[nb][3] * inv1;
        *(float2*)(O1 + nb * 8 + 2 * tg) = o1;
    }
}

// ---------------------------------------------------------------------------
extern "C" void kernel_launch(void* const* d_in, const int* in_sizes, int n_in,
                              void* d_out, int out_size)
{
    const float* x      = (const float*)d_in[0];
    const int*   pmask  = (const int*)d_in[1];
    const float* alibi  = (const float*)d_in[2];
    const float* qkv_w  = (const float*)d_in[3];
    const float* qkv_b  = (const float*)d_in[4];
    const float* proj_w = (const float*)d_in[5];
    const float* proj_b = (const float*)d_in[6];
    float*       out    = (float*)d_out;

    // 1) QKV projection (fp32 FFMA, unchanged)
    sgemm_kernel<0><<<dim3(2304 / 128, (BB * NN) / 128), 256>>>(
        x, qkv_w, qkv_b, nullptr, CC, 3 * CC);

    // 2) Flash attention on tensor pipe (tf32 mma)
    const int attn_smem = (2 * 64 * 68 + 64 * 72 + 64 * 68) * 4;  // 70656 B
    cudaFuncSetAttribute(attn_mma_kernel,
                         cudaFuncAttributeMaxDynamicSharedMemorySize, attn_smem);
    attn_mma_kernel<<<dim3(NN / 64, HH, BB), 128, attn_smem>>>(alibi, pmask);

    // 3) Output projection (fp32 FFMA, unchanged)
    sgemm_kernel<1><<<dim3(CC / 128, (BB * NN) / 128), 256>>>(
        nullptr, proj_w, proj_b, out, CC, CC);
}

// round 5
// speedup vs baseline: 2.5665x; 1.5497x over previous
#include <cuda_runtime.h>
#include <cstdint>
#include <cstddef>

// Problem constants
#define BB 4
#define NN 2048
#define CC 768
#define HH 12
#define DD 64

// Scratch (allocation-free rule: __device__ globals)
__device__ float g_Q[(size_t)BB * HH * NN * DD];   // pre-scaled by D^-0.5
__device__ float g_K[(size_t)BB * HH * NN * DD];
__device__ float g_V[(size_t)BB * HH * NN * DD];
__device__ float g_O[(size_t)BB * NN * CC];        // [B,N,C] attention output

// ---------------------------------------------------------------------------
// tf32 helpers
// ---------------------------------------------------------------------------
__device__ __forceinline__ uint32_t f2tf(float x) {
    uint32_t r;
    asm("cvt.rna.tf32.f32 %0, %1;" : "=r"(r) : "f"(x));
    return r;
}

__device__ __forceinline__ void mma_tf32(float c[4], const uint32_t a[4],
                                         const uint32_t b[2]) {
    asm volatile(
        "mma.sync.aligned.m16n8k8.row.col.f32.tf32.tf32.f32 "
        "{%0,%1,%2,%3}, {%4,%5,%6,%7}, {%8,%9}, {%0,%1,%2,%3};\n"
        : "+f"(c[0]), "+f"(c[1]), "+f"(c[2]), "+f"(c[3])
        : "r"(a[0]), "r"(a[1]), "r"(a[2]), "r"(a[3]),
          "r"(b[0]), "r"(b[1]));
}

// ---------------------------------------------------------------------------
// tf32 tensor-core GEMM: C[M,Nw] = A[M,K] @ W[K,Nw] + bias
// 128x128 tile, BK=32, 256 thr = 8 warps (2m x 4n), warp = 64x32 via m16n8k8.
// Smem stride 36 words: fragment loads hit banks 4g+tg -> conflict-free.
// MODE 0: epilogue scatters into g_Q/g_K/g_V ([B,H,N,D], Q scaled 0.125)
// MODE 1: A is g_O, epilogue writes Cout[row*Nw+col]
// ---------------------------------------------------------------------------
template <int MODE>
__global__ __launch_bounds__(256) void mma_gemm_kernel(
    const float* __restrict__ A, const float* __restrict__ W,
    const float* __restrict__ bias, float* __restrict__ Cout,
    int K, int Nw)
{
    __shared__ uint32_t As[128 * 36];   // [m][k] tf32
    __shared__ uint32_t Bs[128 * 36];   // [n][k] tf32 (W transposed)

    const float* Ap = (MODE == 1) ? (const float*)g_O : A;

    const int tid  = threadIdx.x;
    const int brow = blockIdx.y;
    const int bcol = blockIdx.x;
    const int warp = tid >> 5, lane = tid & 31;
    const int g = lane >> 2, tg = lane & 3;
    const int wm = warp & 1, wn = warp >> 1;
    const int m_base = wm * 64, n_base = wn * 32;

    const float* Ablk = Ap + (size_t)(brow * 128) * K;
    const float* Wblk = W + bcol * 128;

    // Load mappings
    const int la_m = tid >> 1;           // 0..127
    const int la_k = (tid & 1) * 16;     // 0 or 16
    const int lb_n = (tid & 63) * 2;     // 0..126 step 2
    const int lb_k = (tid >> 6) * 8;     // 0,8,16,24

    float acc[4][4][4];
    #pragma unroll
    for (int mt = 0; mt < 4; mt++)
        #pragma unroll
        for (int nt = 0; nt < 4; nt++)
            #pragma unroll
            for (int c = 0; c < 4; c++) acc[mt][nt][c] = 0.f;

    for (int k0 = 0; k0 < K; k0 += 32) {
        // Fill A tile: 4 float4 per thread, k-contiguous
        #pragma unroll
        for (int j = 0; j < 4; j++) {
            float4 v = *(const float4*)(Ablk + (size_t)la_m * K + k0 + la_k + j * 4);
            uint4 u;
            u.x = f2tf(v.x); u.y = f2tf(v.y); u.z = f2tf(v.z); u.w = f2tf(v.w);
            *(uint4*)&As[la_m * 36 + la_k + j * 4] = u;
        }
        // Fill B tile transposed: n-coalesced float2 gmem reads, [n][k] stores
        uint32_t bt0[8], bt1[8];
        #pragma unroll
        for (int j = 0; j < 8; j++) {
            float2 v = *(const float2*)(Wblk + (size_t)(k0 + lb_k + j) * Nw + lb_n);
            bt0[j] = f2tf(v.x);
            bt1[j] = f2tf(v.y);
        }
        *(uint4*)&Bs[lb_n * 36 + lb_k]           = *(uint4*)&bt0[0];
        *(uint4*)&Bs[lb_n * 36 + lb_k + 4]       = *(uint4*)&bt0[4];
        *(uint4*)&Bs[(lb_n + 1) * 36 + lb_k]     = *(uint4*)&bt1[0];
        *(uint4*)&Bs[(lb_n + 1) * 36 + lb_k + 4] = *(uint4*)&bt1[4];
        __syncthreads();

        #pragma unroll
        for (int ks = 0; ks < 4; ks++) {
            const int kk = ks * 8;
            uint32_t af[4][4], bf[4][2];
            #pragma unroll
            for (int mt = 0; mt < 4; mt++) {
                int r = m_base + mt * 16;
                af[mt][0] = As[(r + g)     * 36 + kk + tg];
                af[mt][1] = As[(r + g + 8) * 36 + kk + tg];
                af[mt][2] = As[(r + g)     * 36 + kk + tg + 4];
                af[mt][3] = As[(r + g + 8) * 36 + kk + tg + 4];
            }
            #pragma unroll
            for (int nt = 0; nt < 4; nt++) {
                int c = n_base + nt * 8;
                bf[nt][0] = Bs[(c + g) * 36 + kk + tg];
                bf[nt][1] = Bs[(c + g) * 36 + kk + tg + 4];
            }
            #pragma unroll
            for (int mt = 0; mt < 4; mt++)
                #pragma unroll
                for (int nt = 0; nt < 4; nt++)
                    mma_tf32(acc[mt][nt], af[mt], bf[nt]);
        }
        __syncthreads();
    }

    // Epilogue
    #pragma unroll
    for (int mt = 0; mt < 4; mt++) {
        #pragma unroll
        for (int nt = 0; nt < 4; nt++) {
            #pragma unroll
            for (int half = 0; half < 2; half++) {
                int row = brow * 128 + m_base + mt * 16 + g + half * 8;
                int col = bcol * 128 + n_base + nt * 8 + 2 * tg;
                float v0 = acc[mt][nt][2 * half + 0] + bias[col];
                float v1 = acc[mt][nt][2 * half + 1] + bias[col + 1];
                if (MODE == 0) {
                    #pragma unroll
                    for (int e = 0; e < 2; e++) {
                        int cc2 = col + e;
                        float v = e ? v1 : v0;
                        int t   = cc2 / CC;
                        int rem = cc2 - t * CC;
                        int h   = rem >> 6;
                        int d   = rem & 63;
                        int bI  = row >> 11;
                        int n   = row & 2047;
                        size_t idx = (((size_t)bI * HH + h) * NN + n) * DD + d;
                        if (t == 0)      g_Q[idx] = v * 0.125f;
                        else if (t == 1) g_K[idx] = v;
                        else             g_V[idx] = v;
                    }
                } else {
                    float2 o; o.x = v0; o.y = v1;
                    *(float2*)(Cout + (size_t)row * Nw + col) = o;
                }
            }
        }
    }
}

// ---------------------------------------------------------------------------
// Flash attention on tensor pipe (mma.sync m16n8k8 tf32). Unchanged.
// ---------------------------------------------------------------------------
__global__ __launch_bounds__(128) void attn_mma_kernel(
    const float* __restrict__ alibi, const int* __restrict__ mask)
{
    extern __shared__ uint32_t smem[];
    uint32_t* Qs = smem;                        // [64][68] tf32
    uint32_t* Ks = smem + 64 * 68;              // [64][68] tf32
    uint32_t* Vs = smem + 2 * 64 * 68;          // [64][72] tf32
    uint32_t* Ps = smem + 2 * 64 * 68 + 64 * 72;// [64][68] tf32

    const int b = blockIdx.z, h = blockIdx.y;
    const int q0 = blockIdx.x * 64;
    const int tid = threadIdx.x;
    const int warp = tid >> 5, lane = tid & 31;
    const int g = lane >> 2, tg = lane & 3;
    const int m0w = warp * 16;

    size_t bh = (size_t)b * HH + h;
    const float* Qg = g_Q + (bh * NN + q0) * DD;
    const float* Kg = g_K + bh * NN * DD;
    const float* Vg = g_V + bh * NN * DD;
    const float* alibi_bh = alibi + (bh * NN + q0) * (size_t)NN;
    const int* mask_b = mask + (size_t)b * NN;

    for (int i = tid; i < 64 * 16; i += 128) {
        int r = i >> 4, c4 = (i & 15) << 2;
        float4 q = *(const float4*)(Qg + (size_t)r * DD + c4);
        Qs[r * 68 + c4 + 0] = f2tf(q.x);
        Qs[r * 68 + c4 + 1] = f2tf(q.y);
        Qs[r * 68 + c4 + 2] = f2tf(q.z);
        Qs[r * 68 + c4 + 3] = f2tf(q.w);
    }

    float oacc[8][4];
    #pragma unroll
    for (int nb = 0; nb < 8; nb++)
        #pragma unroll
        for (int c = 0; c < 4; c++) oacc[nb][c] = 0.f;

    float mi0 = -1e30f, mi1 = -1e30f, li0 = 0.f, li1 = 0.f;

    for (int kt = 0; kt < NN / 64; kt++) {
        const int m0 = kt * 64;
        __syncthreads();
        for (int i = tid; i < 64 * 16; i += 128) {
            int r = i >> 4, c4 = (i & 15) << 2;
            float4 kv = *(const float4*)(Kg + (size_t)(m0 + r) * DD + c4);
            Ks[r * 68 + c4 + 0] = f2tf(kv.x);
            Ks[r * 68 + c4 + 1] = f2tf(kv.y);
            Ks[r * 68 + c4 + 2] = f2tf(kv.z);
            Ks[r * 68 + c4 + 3] = f2tf(kv.w);
            float4 vv = *(const float4*)(Vg + (size_t)(m0 + r) * DD + c4);
            Vs[r * 72 + c4 + 0] = f2tf(vv.x);
            Vs[r * 72 + c4 + 1] = f2tf(vv.y);
            Vs[r * 72 + c4 + 2] = f2tf(vv.z);
            Vs[r * 72 + c4 + 3] = f2tf(vv.w);
        }
        __syncthreads();

        float sacc[8][4];
        #pragma unroll
        for (int nb = 0; nb < 8; nb++)
            #pragma unroll
            for (int c = 0; c < 4; c++) sacc[nb][c] = 0.f;

        #pragma unroll
        for (int kk = 0; kk < 8; kk++) {
            const int ak = kk * 8;
            uint32_t a[4];
            a[0] = Qs[(m0w + g)     * 68 + ak + tg];
            a[1] = Qs[(m0w + g + 8) * 68 + ak + tg];
            a[2] = Qs[(m0w + g)     * 68 + ak + tg + 4];
            a[3] = Qs[(m0w + g + 8) * 68 + ak + tg + 4];
            #pragma unroll
            for (int nb = 0; nb < 8; nb++) {
                uint32_t bf[2];
                bf[0] = Ks[(nb * 8 + g) * 68 + ak + tg];
                bf[1] = Ks[(nb * 8 + g) * 68 + ak + tg + 4];
                mma_tf32(sacc[nb], a, bf);
            }
        }

        float tm0 = -1e30f, tm1 = -1e30f;
        #pragma unroll
        for (int nb = 0; nb < 8; nb++) {
            int col = m0 + nb * 8 + 2 * tg;
            float2 al0 = *(const float2*)(alibi_bh + (size_t)(m0w + g) * NN + col);
            float2 al1 = *(const float2*)(alibi_bh + (size_t)(m0w + g + 8) * NN + col);
            int2 mk = *(const int2*)(mask_b + col);
            sacc[nb][0] = mk.x ? -1e30f : sacc[nb][0] + al0.x;
            sacc[nb][1] = mk.y ? -1e30f : sacc[nb][1] + al0.y;
            sacc[nb][2] = mk.x ? -1e30f : sacc[nb][2] + al1.x;
            sacc[nb][3] = mk.y ? -1e30f : sacc[nb][3] + al1.y;
            tm0 = fmaxf(tm0, fmaxf(sacc[nb][0], sacc[nb][1]));
            tm1 = fmaxf(tm1, fmaxf(sacc[nb][2], sacc[nb][3]));
        }
        tm0 = fmaxf(tm0, __shfl_xor_sync(0xffffffffu, tm0, 1));
        tm0 = fmaxf(tm0, __shfl_xor_sync(0xffffffffu, tm0, 2));
        tm1 = fmaxf(tm1, __shfl_xor_sync(0xffffffffu, tm1, 1));
        tm1 = fmaxf(tm1, __shfl_xor_sync(0xffffffffu, tm1, 2));

        float mn0 = fmaxf(mi0, tm0), mn1 = fmaxf(mi1, tm1);
        float a0 = __expf(mi0 - mn0), a1 = __expf(mi1 - mn1);
        float sum0 = 0.f, sum1 = 0.f;
        #pragma unroll
        for (int nb = 0; nb < 8; nb++) {
            float p00 = __expf(sacc[nb][0] - mn0);
            float p01 = __expf(sacc[nb][1] - mn0);
            float p10 = __expf(sacc[nb][2] - mn1);
            float p11 = __expf(sacc[nb][3] - mn1);
            sum0 += p00 + p01;
            sum1 += p10 + p11;
            uint2 w0; w0.x = f2tf(p00); w0.y = f2tf(p01);
            *(uint2*)&Ps[(m0w + g) * 68 + nb * 8 + 2 * tg] = w0;
            uint2 w1; w1.x = f2tf(p10); w1.y = f2tf(p11);
            *(uint2*)&Ps[(m0w + g + 8) * 68 + nb * 8 + 2 * tg] = w1;
            oacc[nb][0] *= a0; oacc[nb][1] *= a0;
            oacc[nb][2] *= a1; oacc[nb][3] *= a1;
        }
        sum0 += __shfl_xor_sync(0xffffffffu, sum0, 1);
        sum0 += __shfl_xor_sync(0xffffffffu, sum0, 2);
        sum1 += __shfl_xor_sync(0xffffffffu, sum1, 1);
        sum1 += __shfl_xor_sync(0xffffffffu, sum1, 2);
        li0 = li0 * a0 + sum0;
        li1 = li1 * a1 + sum1;
        mi0 = mn0; mi1 = mn1;
        __syncwarp();

        #pragma unroll
        for (int kk = 0; kk < 8; kk++) {
            const int kp = kk * 8;
            uint32_t a[4];
            a[0] = Ps[(m0w + g)     * 68 + kp + tg];
            a[1] = Ps[(m0w + g + 8) * 68 + kp + tg];
            a[2] = Ps[(m0w + g)     * 68 + kp + tg + 4];
            a[3] = Ps[(m0w + g + 8) * 68 + kp + tg + 4];
            #pragma unroll
            for (int nb = 0; nb < 8; nb++) {
                uint32_t bf[2];
                bf[0] = Vs[(kp + tg)     * 72 + nb * 8 + g];
                bf[1] = Vs[(kp + tg + 4) * 72 + nb * 8 + g];
                mma_tf32(oacc[nb], a, bf);
            }
        }
    }

    float inv0 = 1.f / li0, inv1 = 1.f / li1;
    float* O0 = g_O + ((size_t)b * NN + q0 + m0w + g) * CC + h * DD;
    float* O1 = O0 + 8 * (size_t)CC;
    #pragma unroll
    for (int nb = 0; nb < 8; nb++) {
        float2 o0; o0.x = oacc[nb][0] * inv0; o0.y = oacc[nb][1] * inv0;
        *(float2*)(O0 + nb * 8 + 2 * tg) = o0;
        float2 o1; o1.x = oacc[nb][2] * inv1; o1.y = oacc[nb][3] * inv1;
        *(float2*)(O1 + nb * 8 + 2 * tg) = o1;
    }
}

// ---------------------------------------------------------------------------
extern "C" void kernel_launch(void* const* d_in, const int* in_sizes, int n_in,
                              void* d_out, int out_size)
{
    const float* x      = (const float*)d_in[0];
    const int*   pmask  = (const int*)d_in[1];
    const float* alibi  = (const float*)d_in[2];
    const float* qkv_w  = (const float*)d_in[3];
    const float* qkv_b  = (const float*)d_in[4];
    const float* proj_w = (const float*)d_in[5];
    const float* proj_b = (const float*)d_in[6];
    float*       out    = (float*)d_out;

    // 1) QKV projection on tensor pipe (tf32)
    mma_gemm_kernel<0><<<dim3(2304 / 128, (BB * NN) / 128), 256>>>(
        x, qkv_w, qkv_b, nullptr, CC, 3 * CC);

    // 2) Flash attention on tensor pipe (tf32 mma)
    const int attn_smem = (2 * 64 * 68 + 64 * 72 + 64 * 68) * 4;  // 70656 B
    cudaFuncSetAttribute(attn_mma_kernel,
                         cudaFuncAttributeMaxDynamicSharedMemorySize, attn_smem);
    attn_mma_kernel<<<dim3(NN / 64, HH, BB), 128, attn_smem>>>(alibi, pmask);

    // 3) Output projection on tensor pipe (tf32)
    mma_gemm_kernel<1><<<dim3(CC / 128, (BB * NN) / 128), 256>>>(
        nullptr, proj_w, proj_b, out, CC, CC);
}

// round 6
// speedup vs baseline: 3.1330x; 1.2207x over previous
#include <cuda_runtime.h>
#include <cstdint>
#include <cstddef>

// Problem constants
#define BB 4
#define NN 2048
#define CC 768
#define HH 12
#define DD 64

// Scratch (allocation-free rule: __device__ globals)
__device__ float g_Q[(size_t)BB * HH * NN * DD];   // pre-scaled by D^-0.5
__device__ float g_K[(size_t)BB * HH * NN * DD];
__device__ float g_V[(size_t)BB * HH * NN * DD];
__device__ float g_O[(size_t)BB * NN * CC];        // [B,N,C] attention output

// ---------------------------------------------------------------------------
// tf32 helpers
// ---------------------------------------------------------------------------
__device__ __forceinline__ uint32_t f2tf(float x) {
    uint32_t r;
    asm("cvt.rna.tf32.f32 %0, %1;" : "=r"(r) : "f"(x));
    return r;
}

__device__ __forceinline__ void mma_tf32(float c[4], const uint32_t a[4],
                                         const uint32_t b[2]) {
    asm volatile(
        "mma.sync.aligned.m16n8k8.row.col.f32.tf32.tf32.f32 "
        "{%0,%1,%2,%3}, {%4,%5,%6,%7}, {%8,%9}, {%0,%1,%2,%3};\n"
        : "+f"(c[0]), "+f"(c[1]), "+f"(c[2]), "+f"(c[3])
        : "r"(a[0]), "r"(a[1]), "r"(a[2]), "r"(a[3]),
          "r"(b[0]), "r"(b[1]));
}

// ---------------------------------------------------------------------------
// tf32 tensor-core GEMM (unchanged): 128x128 tile, BK=32, 256 thr, 8 warps.
// ---------------------------------------------------------------------------
template <int MODE>
__global__ __launch_bounds__(256) void mma_gemm_kernel(
    const float* __restrict__ A, const float* __restrict__ W,
    const float* __restrict__ bias, float* __restrict__ Cout,
    int K, int Nw)
{
    __shared__ uint32_t As[128 * 36];   // [m][k] tf32
    __shared__ uint32_t Bs[128 * 36];   // [n][k] tf32 (W transposed)

    const float* Ap = (MODE == 1) ? (const float*)g_O : A;

    const int tid  = threadIdx.x;
    const int brow = blockIdx.y;
    const int bcol = blockIdx.x;
    const int warp = tid >> 5, lane = tid & 31;
    const int g = lane >> 2, tg = lane & 3;
    const int wm = warp & 1, wn = warp >> 1;
    const int m_base = wm * 64, n_base = wn * 32;

    const float* Ablk = Ap + (size_t)(brow * 128) * K;
    const float* Wblk = W + bcol * 128;

    const int la_m = tid >> 1;
    const int la_k = (tid & 1) * 16;
    const int lb_n = (tid & 63) * 2;
    const int lb_k = (tid >> 6) * 8;

    float acc[4][4][4];
    #pragma unroll
    for (int mt = 0; mt < 4; mt++)
        #pragma unroll
        for (int nt = 0; nt < 4; nt++)
            #pragma unroll
            for (int c = 0; c < 4; c++) acc[mt][nt][c] = 0.f;

    for (int k0 = 0; k0 < K; k0 += 32) {
        #pragma unroll
        for (int j = 0; j < 4; j++) {
            float4 v = *(const float4*)(Ablk + (size_t)la_m * K + k0 + la_k + j * 4);
            uint4 u;
            u.x = f2tf(v.x); u.y = f2tf(v.y); u.z = f2tf(v.z); u.w = f2tf(v.w);
            *(uint4*)&As[la_m * 36 + la_k + j * 4] = u;
        }
        uint32_t bt0[8], bt1[8];
        #pragma unroll
        for (int j = 0; j < 8; j++) {
            float2 v = *(const float2*)(Wblk + (size_t)(k0 + lb_k + j) * Nw + lb_n);
            bt0[j] = f2tf(v.x);
            bt1[j] = f2tf(v.y);
        }
        *(uint4*)&Bs[lb_n * 36 + lb_k]           = *(uint4*)&bt0[0];
        *(uint4*)&Bs[lb_n * 36 + lb_k + 4]       = *(uint4*)&bt0[4];
        *(uint4*)&Bs[(lb_n + 1) * 36 + lb_k]     = *(uint4*)&bt1[0];
        *(uint4*)&Bs[(lb_n + 1) * 36 + lb_k + 4] = *(uint4*)&bt1[4];
        __syncthreads();

        #pragma unroll
        for (int ks = 0; ks < 4; ks++) {
            const int kk = ks * 8;
            uint32_t af[4][4], bf[4][2];
            #pragma unroll
            for (int mt = 0; mt < 4; mt++) {
                int r = m_base + mt * 16;
                af[mt][0] = As[(r + g)     * 36 + kk + tg];
                af[mt][1] = As[(r + g + 8) * 36 + kk + tg];
                af[mt][2] = As[(r + g)     * 36 + kk + tg + 4];
                af[mt][3] = As[(r + g + 8) * 36 + kk + tg + 4];
            }
            #pragma unroll
            for (int nt = 0; nt < 4; nt++) {
                int c = n_base + nt * 8;
                bf[nt][0] = Bs[(c + g) * 36 + kk + tg];
                bf[nt][1] = Bs[(c + g) * 36 + kk + tg + 4];
            }
            #pragma unroll
            for (int mt = 0; mt < 4; mt++)
                #pragma unroll
                for (int nt = 0; nt < 4; nt++)
                    mma_tf32(acc[mt][nt], af[mt], bf[nt]);
        }
        __syncthreads();
    }

    #pragma unroll
    for (int mt = 0; mt < 4; mt++) {
        #pragma unroll
        for (int nt = 0; nt < 4; nt++) {
            #pragma unroll
            for (int half = 0; half < 2; half++) {
                int row = brow * 128 + m_base + mt * 16 + g + half * 8;
                int col = bcol * 128 + n_base + nt * 8 + 2 * tg;
                float v0 = acc[mt][nt][2 * half + 0] + bias[col];
                float v1 = acc[mt][nt][2 * half + 1] + bias[col + 1];
                if (MODE == 0) {
                    #pragma unroll
                    for (int e = 0; e < 2; e++) {
                        int cc2 = col + e;
                        float v = e ? v1 : v0;
                        int t   = cc2 / CC;
                        int rem = cc2 - t * CC;
                        int h   = rem >> 6;
                        int d   = rem & 63;
                        int bI  = row >> 11;
                        int n   = row & 2047;
                        size_t idx = (((size_t)bI * HH + h) * NN + n) * DD + d;
                        if (t == 0)      g_Q[idx] = v * 0.125f;
                        else if (t == 1) g_K[idx] = v;
                        else             g_V[idx] = v;
                    }
                } else {
                    float2 o; o.x = v0; o.y = v1;
                    *(float2*)(Cout + (size_t)row * Nw + col) = o;
                }
            }
        }
    }
}

// ---------------------------------------------------------------------------
// Flash attention v2: Q fragments in registers (loaded once), smem holds only
// K/V/P -> 53248 B -> 3 CTAs/SM. CTA: 4 warps x 16 query rows, BN=64.
// ---------------------------------------------------------------------------
__global__ __launch_bounds__(128, 3) void attn_mma_kernel(
    const float* __restrict__ alibi, const int* __restrict__ mask)
{
    extern __shared__ uint32_t smem[];
    uint32_t* Ks = smem;                        // [64][68] tf32 (Q staged here first)
    uint32_t* Vs = smem + 64 * 68;              // [64][72] tf32
    uint32_t* Ps = smem + 64 * 68 + 64 * 72;    // [64][68] tf32

    const int b = blockIdx.z, h = blockIdx.y;
    const int q0 = blockIdx.x * 64;
    const int tid = threadIdx.x;
    const int warp = tid >> 5, lane = tid & 31;
    const int g = lane >> 2, tg = lane & 3;
    const int m0w = warp * 16;

    size_t bh = (size_t)b * HH + h;
    const float* Qg = g_Q + (bh * NN + q0) * DD;
    const float* Kg = g_K + bh * NN * DD;
    const float* Vg = g_V + bh * NN * DD;
    const float* alibi_bh = alibi + (bh * NN + q0) * (size_t)NN;
    const int* mask_b = mask + (size_t)b * NN;

    // Prologue: stage Q through Ks buffer, pull A-fragments into registers
    for (int i = tid; i < 64 * 16; i += 128) {
        int r = i >> 4, c4 = (i & 15) << 2;
        float4 q = *(const float4*)(Qg + (size_t)r * DD + c4);
        Ks[r * 68 + c4 + 0] = f2tf(q.x);
        Ks[r * 68 + c4 + 1] = f2tf(q.y);
        Ks[r * 68 + c4 + 2] = f2tf(q.z);
        Ks[r * 68 + c4 + 3] = f2tf(q.w);
    }
    __syncthreads();
    uint32_t qf[8][4];
    #pragma unroll
    for (int kk = 0; kk < 8; kk++) {
        const int ak = kk * 8;
        qf[kk][0] = Ks[(m0w + g)     * 68 + ak + tg];
        qf[kk][1] = Ks[(m0w + g + 8) * 68 + ak + tg];
        qf[kk][2] = Ks[(m0w + g)     * 68 + ak + tg + 4];
        qf[kk][3] = Ks[(m0w + g + 8) * 68 + ak + tg + 4];
    }

    float oacc[8][4];
    #pragma unroll
    for (int nb = 0; nb < 8; nb++)
        #pragma unroll
        for (int c = 0; c < 4; c++) oacc[nb][c] = 0.f;

    float mi0 = -1e30f, mi1 = -1e30f, li0 = 0.f, li1 = 0.f;

    for (int kt = 0; kt < NN / 64; kt++) {
        const int m0 = kt * 64;
        __syncthreads();   // Q-frag reads done (iter 0) / prior tile consumed
        for (int i = tid; i < 64 * 16; i += 128) {
            int r = i >> 4, c4 = (i & 15) << 2;
            float4 kv = *(const float4*)(Kg + (size_t)(m0 + r) * DD + c4);
            Ks[r * 68 + c4 + 0] = f2tf(kv.x);
            Ks[r * 68 + c4 + 1] = f2tf(kv.y);
            Ks[r * 68 + c4 + 2] = f2tf(kv.z);
            Ks[r * 68 + c4 + 3] = f2tf(kv.w);
            float4 vv = *(const float4*)(Vg + (size_t)(m0 + r) * DD + c4);
            Vs[r * 72 + c4 + 0] = f2tf(vv.x);
            Vs[r * 72 + c4 + 1] = f2tf(vv.y);
            Vs[r * 72 + c4 + 2] = f2tf(vv.z);
            Vs[r * 72 + c4 + 3] = f2tf(vv.w);
        }
        __syncthreads();

        // --- S = Q K^T (Q from registers) ---
        float sacc[8][4];
        #pragma unroll
        for (int nb = 0; nb < 8; nb++)
            #pragma unroll
            for (int c = 0; c < 4; c++) sacc[nb][c] = 0.f;

        #pragma unroll
        for (int kk = 0; kk < 8; kk++) {
            const int ak = kk * 8;
            #pragma unroll
            for (int nb = 0; nb < 8; nb++) {
                uint32_t bf[2];
                bf[0] = Ks[(nb * 8 + g) * 68 + ak + tg];
                bf[1] = Ks[(nb * 8 + g) * 68 + ak + tg + 4];
                mma_tf32(sacc[nb], qf[kk], bf);
            }
        }

        // --- alibi + mask, tile max ---
        float tm0 = -1e30f, tm1 = -1e30f;
        #pragma unroll
        for (int nb = 0; nb < 8; nb++) {
            int col = m0 + nb * 8 + 2 * tg;
            float2 al0 = *(const float2*)(alibi_bh + (size_t)(m0w + g) * NN + col);
            float2 al1 = *(const float2*)(alibi_bh + (size_t)(m0w + g + 8) * NN + col);
            int2 mk = *(const int2*)(mask_b + col);
            sacc[nb][0] = mk.x ? -1e30f : sacc[nb][0] + al0.x;
            sacc[nb][1] = mk.y ? -1e30f : sacc[nb][1] + al0.y;
            sacc[nb][2] = mk.x ? -1e30f : sacc[nb][2] + al1.x;
            sacc[nb][3] = mk.y ? -1e30f : sacc[nb][3] + al1.y;
            tm0 = fmaxf(tm0, fmaxf(sacc[nb][0], sacc[nb][1]));
            tm1 = fmaxf(tm1, fmaxf(sacc[nb][2], sacc[nb][3]));
        }
        tm0 = fmaxf(tm0, __shfl_xor_sync(0xffffffffu, tm0, 1));
        tm0 = fmaxf(tm0, __shfl_xor_sync(0xffffffffu, tm0, 2));
        tm1 = fmaxf(tm1, __shfl_xor_sync(0xffffffffu, tm1, 1));
        tm1 = fmaxf(tm1, __shfl_xor_sync(0xffffffffu, tm1, 2));

        // --- online softmax ---
        float mn0 = fmaxf(mi0, tm0), mn1 = fmaxf(mi1, tm1);
        float a0 = __expf(mi0 - mn0), a1 = __expf(mi1 - mn1);
        float sum0 = 0.f, sum1 = 0.f;
        #pragma unroll
        for (int nb = 0; nb < 8; nb++) {
            float p00 = __expf(sacc[nb][0] - mn0);
            float p01 = __expf(sacc[nb][1] - mn0);
            float p10 = __expf(sacc[nb][2] - mn1);
            float p11 = __expf(sacc[nb][3] - mn1);
            sum0 += p00 + p01;
            sum1 += p10 + p11;
            uint2 w0; w0.x = f2tf(p00); w0.y = f2tf(p01);
            *(uint2*)&Ps[(m0w + g) * 68 + nb * 8 + 2 * tg] = w0;
            uint2 w1; w1.x = f2tf(p10); w1.y = f2tf(p11);
            *(uint2*)&Ps[(m0w + g + 8) * 68 + nb * 8 + 2 * tg] = w1;
            oacc[nb][0] *= a0; oacc[nb][1] *= a0;
            oacc[nb][2] *= a1; oacc[nb][3] *= a1;
        }
        sum0 += __shfl_xor_sync(0xffffffffu, sum0, 1);
        sum0 += __shfl_xor_sync(0xffffffffu, sum0, 2);
        sum1 += __shfl_xor_sync(0xffffffffu, sum1, 1);
        sum1 += __shfl_xor_sync(0xffffffffu, sum1, 2);
        li0 = li0 * a0 + sum0;
        li1 = li1 * a1 + sum1;
        mi0 = mn0; mi1 = mn1;
        __syncwarp();   // P visible to own warp's A-frag loads

        // --- O += P V ---
        #pragma unroll
        for (int kk = 0; kk < 8; kk++) {
            const int kp = kk * 8;
            uint32_t a[4];
            a[0] = Ps[(m0w + g)     * 68 + kp + tg];
            a[1] = Ps[(m0w + g + 8) * 68 + kp + tg];
            a[2] = Ps[(m0w + g)     * 68 + kp + tg + 4];
            a[3] = Ps[(m0w + g + 8) * 68 + kp + tg + 4];
            #pragma unroll
            for (int nb = 0; nb < 8; nb++) {
                uint32_t bf[2];
                bf[0] = Vs[(kp + tg)     * 72 + nb * 8 + g];
                bf[1] = Vs[(kp + tg + 4) * 72 + nb * 8 + g];
                mma_tf32(oacc[nb], a, bf);
            }
        }
    }

    // Epilogue: normalize, write [B,N,C]
    float inv0 = 1.f / li0, inv1 = 1.f / li1;
    float* O0 = g_O + ((size_t)b * NN + q0 + m0w + g) * CC + h * DD;
    float* O1 = O0 + 8 * (size_t)CC;
    #pragma unroll
    for (int nb = 0; nb < 8; nb++) {
        float2 o0; o0.x = oacc[nb][0] * inv0; o0.y = oacc[nb][1] * inv0;
        *(float2*)(O0 + nb * 8 + 2 * tg) = o0;
        float2 o1; o1.x = oacc[nb][2] * inv1; o1.y = oacc[nb][3] * inv1;
        *(float2*)(O1 + nb * 8 + 2 * tg) = o1;
    }
}

// ---------------------------------------------------------------------------
extern "C" void kernel_launch(void* const* d_in, const int* in_sizes, int n_in,
                              void* d_out, int out_size)
{
    const float* x      = (const float*)d_in[0];
    const int*   pmask  = (const int*)d_in[1];
    const float* alibi  = (const float*)d_in[2];
    const float* qkv_w  = (const float*)d_in[3];
    const float* qkv_b  = (const float*)d_in[4];
    const float* proj_w = (const float*)d_in[5];
    const float* proj_b = (const float*)d_in[6];
    float*       out    = (float*)d_out;

    // 1) QKV projection on tensor pipe (tf32)
    mma_gemm_kernel<0><<<dim3(2304 / 128, (BB * NN) / 128), 256>>>(
        x, qkv_w, qkv_b, nullptr, CC, 3 * CC);

    // 2) Flash attention (Q-in-registers, 3 CTAs/SM)
    const int attn_smem = (64 * 68 + 64 * 72 + 64 * 68) * 4;  // 53248 B
    cudaFuncSetAttribute(attn_mma_kernel,
                         cudaFuncAttributeMaxDynamicSharedMemorySize, attn_smem);
    attn_mma_kernel<<<dim3(NN / 64, HH, BB), 128, attn_smem>>>(alibi, pmask);

    // 3) Output projection on tensor pipe (tf32)
    mma_gemm_kernel<1><<<dim3(CC / 128, (BB * NN) / 128), 256>>>(
        nullptr, proj_w, proj_b, out, CC, CC);
}

// round 7
// speedup vs baseline: 3.6784x; 1.1741x over previous
#include <cuda_runtime.h>
#include <cstdint>
#include <cstddef>

// Problem constants
#define BB 4
#define NN 2048
#define CC 768
#define HH 12
#define DD 64

// Scratch (allocation-free rule: __device__ globals)
__device__ float g_Q[(size_t)BB * HH * NN * DD];   // pre-scaled by D^-0.5, tf32-rounded
__device__ float g_K[(size_t)BB * HH * NN * DD];   // tf32-rounded
__device__ float g_V[(size_t)BB * HH * NN * DD];   // tf32-rounded
__device__ float g_O[(size_t)BB * NN * CC];        // [B,N,C], tf32-rounded
__device__ float g_X[(size_t)BB * NN * CC];        // x, tf32-rounded
__device__ float g_Wq[(size_t)CC * 3 * CC];        // qkv_w, tf32-rounded
__device__ float g_Wp[(size_t)CC * CC];            // proj_w, tf32-rounded

// ---------------------------------------------------------------------------
// helpers
// ---------------------------------------------------------------------------
__device__ __forceinline__ uint32_t f2tf(float x) {
    uint32_t r;
    asm("cvt.rna.tf32.f32 %0, %1;" : "=r"(r) : "f"(x));
    return r;
}
__device__ __forceinline__ float f2tff(float x) { return __uint_as_float(f2tf(x)); }

__device__ __forceinline__ void mma_tf32(float c[4], const uint32_t a[4],
                                         const uint32_t b[2]) {
    asm volatile(
        "mma.sync.aligned.m16n8k8.row.col.f32.tf32.tf32.f32 "
        "{%0,%1,%2,%3}, {%4,%5,%6,%7}, {%8,%9}, {%0,%1,%2,%3};\n"
        : "+f"(c[0]), "+f"(c[1]), "+f"(c[2]), "+f"(c[3])
        : "r"(a[0]), "r"(a[1]), "r"(a[2]), "r"(a[3]),
          "r"(b[0]), "r"(b[1]));
}

__device__ __forceinline__ uint32_t s2u(const void* p) {
    return (uint32_t)__cvta_generic_to_shared(p);
}
__device__ __forceinline__ void cp16(uint32_t dst, const void* src) {
    asm volatile("cp.async.cg.shared.global [%0], [%1], 16;" :: "r"(dst), "l"(src));
}
__device__ __forceinline__ void cp_commit() {
    asm volatile("cp.async.commit_group;");
}
template <int N>
__device__ __forceinline__ void cp_wait() {
    asm volatile("cp.async.wait_group %0;" :: "n"(N));
}

// ---------------------------------------------------------------------------
// Pre-rounding pass: out[i] = tf32_rna(in[i])
// ---------------------------------------------------------------------------
__global__ void round_copy_kernel(const float* __restrict__ in,
                                  float* __restrict__ out, int n4)
{
    int i = (blockIdx.x * 256 + threadIdx.x);
    if (i < n4) {
        float4 v = ((const float4*)in)[i];
        v.x = f2tff(v.x); v.y = f2tff(v.y); v.z = f2tff(v.z); v.w = f2tff(v.w);
        ((float4*)out)[i] = v;
    }
}

// ---------------------------------------------------------------------------
// tf32 GEMM, 2-stage cp.async double buffer.
// 128x128 tile, BK=32, 256 thr = 8 warps (2m x 4n), warp = 64x32 m16n8k8.
// As [m][k] stride 36 (banks 4g+tg), Bs [k][n] stride 136 (banks 8tg+g).
// Inputs must be pre-rounded to tf32. MODE 0: scatter Q/K/V; MODE 1: C+bias.
// ---------------------------------------------------------------------------
#define GSTAGE 8960   // words per stage: As 128*36=4608 + Bs 32*136=4352

template <int MODE>
__global__ __launch_bounds__(256) void mma_gemm_kernel(
    const float* __restrict__ A, const float* __restrict__ W,
    const float* __restrict__ bias, float* __restrict__ Cout,
    int K, int Nw)
{
    extern __shared__ uint32_t sm[];

    const float* Ap = (MODE == 1) ? (const float*)g_O : A;

    const int tid  = threadIdx.x;
    const int brow = blockIdx.y;
    const int bcol = blockIdx.x;
    const int warp = tid >> 5, lane = tid & 31;
    const int g = lane >> 2, tg = lane & 3;
    const int wm = warp & 1, wn = warp >> 1;
    const int m_base = wm * 64, n_base = wn * 32;

    const float* Ablk = Ap + (size_t)(brow * 128) * K;
    const float* Wblk = W + bcol * 128;

    const int la_m = tid >> 1;            // 0..127
    const int la_k = (tid & 1) * 16;      // 0 or 16
    const int lb_k = tid >> 3;            // 0..31
    const int lb_n = (tid & 7) * 4;       // 0..28 (word col base)

    float acc[4][4][4];
    #pragma unroll
    for (int mt = 0; mt < 4; mt++)
        #pragma unroll
        for (int nt = 0; nt < 4; nt++)
            #pragma unroll
            for (int c = 0; c < 4; c++) acc[mt][nt][c] = 0.f;

    auto load_stage = [&](int s, int k0) {
        uint32_t* As = sm + s * GSTAGE;
        uint32_t* Bs = sm + s * GSTAGE + 4608;
        const float* a = Ablk + (size_t)la_m * K + k0 + la_k;
        #pragma unroll
        for (int j = 0; j < 2; j++)
            cp16(s2u(&As[la_m * 36 + la_k + j * 4]), a + j * 4);
        #pragma unroll
        for (int j = 2; j < 4; j++)
            cp16(s2u(&As[la_m * 36 + la_k + j * 4]), a + j * 4);
        const float* w = Wblk + (size_t)(k0 + lb_k) * Nw + lb_n;
        #pragma unroll
        for (int j = 0; j < 4; j++)
            cp16(s2u(&Bs[lb_k * 136 + lb_n + j * 32]), w + j * 32);
        cp_commit();
    };

    auto compute = [&](int s) {
        const uint32_t* As = sm + s * GSTAGE;
        const uint32_t* Bs = sm + s * GSTAGE + 4608;
        #pragma unroll
        for (int ks = 0; ks < 4; ks++) {
            const int kk = ks * 8;
            uint32_t af[4][4], bf[4][2];
            #pragma unroll
            for (int mt = 0; mt < 4; mt++) {
                int r = m_base + mt * 16;
                af[mt][0] = As[(r + g)     * 36 + kk + tg];
                af[mt][1] = As[(r + g + 8) * 36 + kk + tg];
                af[mt][2] = As[(r + g)     * 36 + kk + tg + 4];
                af[mt][3] = As[(r + g + 8) * 36 + kk + tg + 4];
            }
            #pragma unroll
            for (int nt = 0; nt < 4; nt++) {
                int c = n_base + nt * 8;
                bf[nt][0] = Bs[(kk + tg)     * 136 + c + g];
                bf[nt][1] = Bs[(kk + tg + 4) * 136 + c + g];
            }
            #pragma unroll
            for (int mt = 0; mt < 4; mt++)
                #pragma unroll
                for (int nt = 0; nt < 4; nt++)
                    mma_tf32(acc[mt][nt], af[mt], bf[nt]);
        }
    };

    const int T = K / 32;
    load_stage(0, 0);
    cp_wait<0>();
    __syncthreads();

    for (int t = 0; t < T; t++) {
        if (t + 1 < T) load_stage((t + 1) & 1, (t + 1) * 32);
        compute(t & 1);
        if (t + 1 < T) { cp_wait<0>(); __syncthreads(); }
    }

    // Epilogue
    #pragma unroll
    for (int mt = 0; mt < 4; mt++) {
        #pragma unroll
        for (int nt = 0; nt < 4; nt++) {
            #pragma unroll
            for (int half = 0; half < 2; half++) {
                int row = brow * 128 + m_base + mt * 16 + g + half * 8;
                int col = bcol * 128 + n_base + nt * 8 + 2 * tg;
                float v0 = acc[mt][nt][2 * half + 0] + bias[col];
                float v1 = acc[mt][nt][2 * half + 1] + bias[col + 1];
                if (MODE == 0) {
                    #pragma unroll
                    for (int e = 0; e < 2; e++) {
                        int cc2 = col + e;
                        float v = e ? v1 : v0;
                        int t2  = cc2 / CC;
                        int rem = cc2 - t2 * CC;
                        int h   = rem >> 6;
                        int d   = rem & 63;
                        int bI  = row >> 11;
                        int n   = row & 2047;
                        size_t idx = (((size_t)bI * HH + h) * NN + n) * DD + d;
                        if (t2 == 0)      g_Q[idx] = f2tff(v) * 0.125f;  // exact pow2
                        else if (t2 == 1) g_K[idx] = f2tff(v);
                        else              g_V[idx] = f2tff(v);
                    }
                } else {
                    float2 o; o.x = v0; o.y = v1;   // final output: no rounding
                    *(float2*)(Cout + (size_t)row * Nw + col) = o;
                }
            }
        }
    }
}

// ---------------------------------------------------------------------------
// Flash attention v3: Q frags in regs; K/V/alibi filled via cp.async
// (alibi parked in Ps buffer during fill, consumed then overwritten by P).
// smem 53248 B -> 3 CTAs/SM. Inputs g_Q/g_K/g_V already tf32-rounded.
// ---------------------------------------------------------------------------
__global__ __launch_bounds__(128, 3) void attn_mma_kernel(
    const float* __restrict__ alibi, const int* __restrict__ mask)
{
    extern __shared__ uint32_t smem[];
    uint32_t* Ks = smem;                        // [64][68]
    uint32_t* Vs = smem + 64 * 68;              // [64][72]
    uint32_t* Ps = smem + 64 * 68 + 64 * 72;    // [64][68]  (alibi, then P)

    const int b = blockIdx.z, h = blockIdx.y;
    const int q0 = blockIdx.x * 64;
    const int tid = threadIdx.x;
    const int warp = tid >> 5, lane = tid & 31;
    const int g = lane >> 2, tg = lane & 3;
    const int m0w = warp * 16;

    size_t bh = (size_t)b * HH + h;
    const float* Qg = g_Q + (bh * NN + q0) * DD;
    const float* Kg = g_K + bh * NN * DD;
    const float* Vg = g_V + bh * NN * DD;
    const float* alibi_bh = alibi + (bh * NN + q0) * (size_t)NN;
    const int* mask_b = mask + (size_t)b * NN;

    // Prologue: stage Q (already tf32) through Ks via cp.async
    #pragma unroll
    for (int it = 0; it < 8; it++) {
        int i = tid + it * 128;
        int r = i >> 4, c4 = (i & 15) << 2;
        cp16(s2u(&Ks[r * 68 + c4]), Qg + (size_t)r * DD + c4);
    }
    cp_commit(); cp_wait<0>();
    __syncthreads();
    uint32_t qf[8][4];
    #pragma unroll
    for (int kk = 0; kk < 8; kk++) {
        const int ak = kk * 8;
        qf[kk][0] = Ks[(m0w + g)     * 68 + ak + tg];
        qf[kk][1] = Ks[(m0w + g + 8) * 68 + ak + tg];
        qf[kk][2] = Ks[(m0w + g)     * 68 + ak + tg + 4];
        qf[kk][3] = Ks[(m0w + g + 8) * 68 + ak + tg + 4];
    }

    float oacc[8][4];
    #pragma unroll
    for (int nb = 0; nb < 8; nb++)
        #pragma unroll
        for (int c = 0; c < 4; c++) oacc[nb][c] = 0.f;

    float mi0 = -1e30f, mi1 = -1e30f, li0 = 0.f, li1 = 0.f;

    for (int kt = 0; kt < NN / 64; kt++) {
        const int m0 = kt * 64;
        __syncthreads();   // Q-frag reads done (iter 0) / prior tile consumed
        #pragma unroll
        for (int it = 0; it < 8; it++) {
            int i = tid + it * 128;
            int r = i >> 4, c4 = (i & 15) << 2;
            cp16(s2u(&Ks[r * 68 + c4]), Kg + (size_t)(m0 + r) * DD + c4);
            cp16(s2u(&Vs[r * 72 + c4]), Vg + (size_t)(m0 + r) * DD + c4);
            cp16(s2u(&Ps[r * 68 + c4]), alibi_bh + (size_t)r * NN + m0 + c4);
        }
        cp_commit(); cp_wait<0>();
        __syncthreads();

        // --- S = Q K^T (Q from registers) ---
        float sacc[8][4];
        #pragma unroll
        for (int nb = 0; nb < 8; nb++)
            #pragma unroll
            for (int c = 0; c < 4; c++) sacc[nb][c] = 0.f;

        #pragma unroll
        for (int kk = 0; kk < 8; kk++) {
            const int ak = kk * 8;
            #pragma unroll
            for (int nb = 0; nb < 8; nb++) {
                uint32_t bf[2];
                bf[0] = Ks[(nb * 8 + g) * 68 + ak + tg];
                bf[1] = Ks[(nb * 8 + g) * 68 + ak + tg + 4];
                mma_tf32(sacc[nb], qf[kk], bf);
            }
        }

        // --- alibi (from smem) + mask, tile max ---
        float tm0 = -1e30f, tm1 = -1e30f;
        #pragma unroll
        for (int nb = 0; nb < 8; nb++) {
            int cl = nb * 8 + 2 * tg;
            float2 al0 = *(const float2*)&Ps[(m0w + g)     * 68 + cl];
            float2 al1 = *(const float2*)&Ps[(m0w + g + 8) * 68 + cl];
            int2 mk = *(const int2*)(mask_b + m0 + cl);
            sacc[nb][0] = mk.x ? -1e30f : sacc[nb][0] + al0.x;
            sacc[nb][1] = mk.y ? -1e30f : sacc[nb][1] + al0.y;
            sacc[nb][2] = mk.x ? -1e30f : sacc[nb][2] + al1.x;
            sacc[nb][3] = mk.y ? -1e30f : sacc[nb][3] + al1.y;
            tm0 = fmaxf(tm0, fmaxf(sacc[nb][0], sacc[nb][1]));
            tm1 = fmaxf(tm1, fmaxf(sacc[nb][2], sacc[nb][3]));
        }
        tm0 = fmaxf(tm0, __shfl_xor_sync(0xffffffffu, tm0, 1));
        tm0 = fmaxf(tm0, __shfl_xor_sync(0xffffffffu, tm0, 2));
        tm1 = fmaxf(tm1, __shfl_xor_sync(0xffffffffu, tm1, 1));
        tm1 = fmaxf(tm1, __shfl_xor_sync(0xffffffffu, tm1, 2));

        // --- online softmax (P overwrites alibi slots, same thread) ---
        float mn0 = fmaxf(mi0, tm0), mn1 = fmaxf(mi1, tm1);
        float a0 = __expf(mi0 - mn0), a1 = __expf(mi1 - mn1);
        float sum0 = 0.f, sum1 = 0.f;
        #pragma unroll
        for (int nb = 0; nb < 8; nb++) {
            float p00 = __expf(sacc[nb][0] - mn0);
            float p01 = __expf(sacc[nb][1] - mn0);
            float p10 = __expf(sacc[nb][2] - mn1);
            float p11 = __expf(sacc[nb][3] - mn1);
            sum0 += p00 + p01;
            sum1 += p10 + p11;
            uint2 w0; w0.x = f2tf(p00); w0.y = f2tf(p01);
            *(uint2*)&Ps[(m0w + g) * 68 + nb * 8 + 2 * tg] = w0;
            uint2 w1; w1.x = f2tf(p10); w1.y = f2tf(p11);
            *(uint2*)&Ps[(m0w + g + 8) * 68 + nb * 8 + 2 * tg] = w1;
            oacc[nb][0] *= a0; oacc[nb][1] *= a0;
            oacc[nb][2] *= a1; oacc[nb][3] *= a1;
        }
        sum0 += __shfl_xor_sync(0xffffffffu, sum0, 1);
        sum0 += __shfl_xor_sync(0xffffffffu, sum0, 2);
        sum1 += __shfl_xor_sync(0xffffffffu, sum1, 1);
        sum1 += __shfl_xor_sync(0xffffffffu, sum1, 2);
        li0 = li0 * a0 + sum0;
        li1 = li1 * a1 + sum1;
        mi0 = mn0; mi1 = mn1;
        __syncwarp();   // P visible to own warp's A-frag loads

        // --- O += P V ---
        #pragma unroll
        for (int kk = 0; kk < 8; kk++) {
            const int kp = kk * 8;
            uint32_t a[4];
            a[0] = Ps[(m0w + g)     * 68 + kp + tg];
            a[1] = Ps[(m0w + g + 8) * 68 + kp + tg];
            a[2] = Ps[(m0w + g)     * 68 + kp + tg + 4];
            a[3] = Ps[(m0w + g + 8) * 68 + kp + tg + 4];
            #pragma unroll
            for (int nb = 0; nb < 8; nb++) {
                uint32_t bf[2];
                bf[0] = Vs[(kp + tg)     * 72 + nb * 8 + g];
                bf[1] = Vs[(kp + tg + 4) * 72 + nb * 8 + g];
                mma_tf32(oacc[nb], a, bf);
            }
        }
    }

    // Epilogue: normalize, round for proj-GEMM consumption, write [B,N,C]
    float inv0 = 1.f / li0, inv1 = 1.f / li1;
    float* O0 = g_O + ((size_t)b * NN + q0 + m0w + g) * CC + h * DD;
    float* O1 = O0 + 8 * (size_t)CC;
    #pragma unroll
    for (int nb = 0; nb < 8; nb++) {
        float2 o0;
        o0.x = f2tff(oacc[nb][0] * inv0);
        o0.y = f2tff(oacc[nb][1] * inv0);
        *(float2*)(O0 + nb * 8 + 2 * tg) = o0;
        float2 o1;
        o1.x = f2tff(oacc[nb][2] * inv1);
        o1.y = f2tff(oacc[nb][3] * inv1);
        *(float2*)(O1 + nb * 8 + 2 * tg) = o1;
    }
}

// ---------------------------------------------------------------------------
extern "C" void kernel_launch(void* const* d_in, const int* in_sizes, int n_in,
                              void* d_out, int out_size)
{
    const float* x      = (const float*)d_in[0];
    const int*   pmask  = (const int*)d_in[1];
    const float* alibi  = (const float*)d_in[2];
    const float* qkv_w  = (const float*)d_in[3];
    const float* qkv_b  = (const float*)d_in[4];
    const float* proj_w = (const float*)d_in[5];
    const float* proj_b = (const float*)d_in[6];
    float*       out    = (float*)d_out;

    float* gx; cudaGetSymbolAddress((void**)&gx, g_X);
    float* gwq; cudaGetSymbolAddress((void**)&gwq, g_Wq);
    float* gwp; cudaGetSymbolAddress((void**)&gwp, g_Wp);

    // 0) Pre-round inputs to tf32 (RNA) once per launch
    {
        int n4x = (BB * NN * CC) / 4;            // 1,572,864
        int n4q = (CC * 3 * CC) / 4;             // 442,368
        int n4p = (CC * CC) / 4;                 // 147,456
        round_copy_kernel<<<(n4x + 255) / 256, 256>>>(x, gx, n4x);
        round_copy_kernel<<<(n4q + 255) / 256, 256>>>(qkv_w, gwq, n4q);
        round_copy_kernel<<<(n4p + 255) / 256, 256>>>(proj_w, gwp, n4p);
    }

    const int gemm_smem = 2 * GSTAGE * 4;        // 71680 B
    cudaFuncSetAttribute(mma_gemm_kernel<0>,
                         cudaFuncAttributeMaxDynamicSharedMemorySize, gemm_smem);
    cudaFuncSetAttribute(mma_gemm_kernel<1>,
                         cudaFuncAttributeMaxDynamicSharedMemorySize, gemm_smem);

    // 1) QKV projection (double-buffered tf32 mma)
    mma_gemm_kernel<0><<<dim3(2304 / 128, (BB * NN) / 128), 256, gemm_smem>>>(
        gx, gwq, qkv_b, nullptr, CC, 3 * CC);

    // 2) Flash attention (cp.async fill, alibi via smem, 3 CTAs/SM)
    const int attn_smem = (64 * 68 + 64 * 72 + 64 * 68) * 4;  // 53248 B
    cudaFuncSetAttribute(attn_mma_kernel,
                         cudaFuncAttributeMaxDynamicSharedMemorySize, attn_smem);
    attn_mma_kernel<<<dim3(NN / 64, HH, BB), 128, attn_smem>>>(alibi, pmask);

    // 3) Output projection
    mma_gemm_kernel<1><<<dim3(CC / 128, (BB * NN) / 128), 256, gemm_smem>>>(
        nullptr, gwp, proj_b, out, CC, CC);
}

// round 8
// speedup vs baseline: 3.8087x; 1.0354x over previous
#include <cuda_runtime.h>
#include <cstdint>
#include <cstddef>

// Problem constants
#define BB 4
#define NN 2048
#define CC 768
#define HH 12
#define DD 64

// Scratch (allocation-free rule: __device__ globals)
__device__ float g_Q[(size_t)BB * HH * NN * DD];   // pre-scaled by D^-0.5, tf32-rounded
__device__ float g_K[(size_t)BB * HH * NN * DD];   // tf32-rounded
__device__ float g_V[(size_t)BB * HH * NN * DD];   // tf32-rounded
__device__ float g_O[(size_t)BB * NN * CC];        // [B,N,C], tf32-rounded
__device__ float g_X[(size_t)BB * NN * CC];        // x, tf32-rounded
__device__ float g_Wq[(size_t)CC * 3 * CC];        // qkv_w, tf32-rounded
__device__ float g_Wp[(size_t)CC * CC];            // proj_w, tf32-rounded

// ---------------------------------------------------------------------------
// helpers
// ---------------------------------------------------------------------------
__device__ __forceinline__ uint32_t f2tf(float x) {
    uint32_t r;
    asm("cvt.rna.tf32.f32 %0, %1;" : "=r"(r) : "f"(x));
    return r;
}
__device__ __forceinline__ float f2tff(float x) { return __uint_as_float(f2tf(x)); }

__device__ __forceinline__ void mma_tf32(float c[4], const uint32_t a[4],
                                         const uint32_t b[2]) {
    asm volatile(
        "mma.sync.aligned.m16n8k8.row.col.f32.tf32.tf32.f32 "
        "{%0,%1,%2,%3}, {%4,%5,%6,%7}, {%8,%9}, {%0,%1,%2,%3};\n"
        : "+f"(c[0]), "+f"(c[1]), "+f"(c[2]), "+f"(c[3])
        : "r"(a[0]), "r"(a[1]), "r"(a[2]), "r"(a[3]),
          "r"(b[0]), "r"(b[1]));
}

__device__ __forceinline__ uint32_t s2u(const void* p) {
    return (uint32_t)__cvta_generic_to_shared(p);
}
__device__ __forceinline__ void cp16(uint32_t dst, const void* src) {
    asm volatile("cp.async.cg.shared.global [%0], [%1], 16;" :: "r"(dst), "l"(src));
}
__device__ __forceinline__ void cp_commit() {
    asm volatile("cp.async.commit_group;");
}
template <int N>
__device__ __forceinline__ void cp_wait() {
    asm volatile("cp.async.wait_group %0;" :: "n"(N));
}

// ---------------------------------------------------------------------------
// Pre-rounding pass: out[i] = tf32_rna(in[i])
// ---------------------------------------------------------------------------
__global__ void round_copy_kernel(const float* __restrict__ in,
                                  float* __restrict__ out, int n4)
{
    int i = (blockIdx.x * 256 + threadIdx.x);
    if (i < n4) {
        float4 v = ((const float4*)in)[i];
        v.x = f2tff(v.x); v.y = f2tff(v.y); v.z = f2tff(v.z); v.w = f2tff(v.w);
        ((float4*)out)[i] = v;
    }
}

// ---------------------------------------------------------------------------
// tf32 GEMM, 3-stage cp.async pipeline.
// 128x128 tile, BK=32, 256 thr = 8 warps (2m x 4n), warp = 64x32 m16n8k8.
// As [m][k] stride 36 (banks 4g+tg), Bs [k][n] stride 136 (banks 8tg+g).
// Inputs must be pre-rounded to tf32. MODE 0: scatter Q/K/V; MODE 1: C+bias.
// ---------------------------------------------------------------------------
#define GSTAGE 8960   // words per stage: As 128*36=4608 + Bs 32*136=4352

template <int MODE>
__global__ __launch_bounds__(256) void mma_gemm_kernel(
    const float* __restrict__ A, const float* __restrict__ W,
    const float* __restrict__ bias, float* __restrict__ Cout,
    int K, int Nw)
{
    extern __shared__ uint32_t sm[];

    const float* Ap = (MODE == 1) ? (const float*)g_O : A;

    const int tid  = threadIdx.x;
    const int brow = blockIdx.y;
    const int bcol = blockIdx.x;
    const int warp = tid >> 5, lane = tid & 31;
    const int g = lane >> 2, tg = lane & 3;
    const int wm = warp & 1, wn = warp >> 1;
    const int m_base = wm * 64, n_base = wn * 32;

    const float* Ablk = Ap + (size_t)(brow * 128) * K;
    const float* Wblk = W + bcol * 128;

    const int la_m = tid >> 1;            // 0..127
    const int la_k = (tid & 1) * 16;      // 0 or 16
    const int lb_k = tid >> 3;            // 0..31
    const int lb_n = (tid & 7) * 4;       // 0..28 (word col base)

    float acc[4][4][4];
    #pragma unroll
    for (int mt = 0; mt < 4; mt++)
        #pragma unroll
        for (int nt = 0; nt < 4; nt++)
            #pragma unroll
            for (int c = 0; c < 4; c++) acc[mt][nt][c] = 0.f;

    auto load_stage = [&](int s, int k0) {
        uint32_t* As = sm + s * GSTAGE;
        uint32_t* Bs = sm + s * GSTAGE + 4608;
        const float* a = Ablk + (size_t)la_m * K + k0 + la_k;
        #pragma unroll
        for (int j = 0; j < 4; j++)
            cp16(s2u(&As[la_m * 36 + la_k + j * 4]), a + j * 4);
        const float* w = Wblk + (size_t)(k0 + lb_k) * Nw + lb_n;
        #pragma unroll
        for (int j = 0; j < 4; j++)
            cp16(s2u(&Bs[lb_k * 136 + lb_n + j * 32]), w + j * 32);
        cp_commit();
    };

    auto compute = [&](int s) {
        const uint32_t* As = sm + s * GSTAGE;
        const uint32_t* Bs = sm + s * GSTAGE + 4608;
        #pragma unroll
        for (int ks = 0; ks < 4; ks++) {
            const int kk = ks * 8;
            uint32_t af[4][4], bf[4][2];
            #pragma unroll
            for (int mt = 0; mt < 4; mt++) {
                int r = m_base + mt * 16;
                af[mt][0] = As[(r + g)     * 36 + kk + tg];
                af[mt][1] = As[(r + g + 8) * 36 + kk + tg];
                af[mt][2] = As[(r + g)     * 36 + kk + tg + 4];
                af[mt][3] = As[(r + g + 8) * 36 + kk + tg + 4];
            }
            #pragma unroll
            for (int nt = 0; nt < 4; nt++) {
                int c = n_base + nt * 8;
                bf[nt][0] = Bs[(kk + tg)     * 136 + c + g];
                bf[nt][1] = Bs[(kk + tg + 4) * 136 + c + g];
            }
            #pragma unroll
            for (int mt = 0; mt < 4; mt++)
                #pragma unroll
                for (int nt = 0; nt < 4; nt++)
                    mma_tf32(acc[mt][nt], af[mt], bf[nt]);
        }
    };

    const int T = K / 32;                 // 24
    load_stage(0, 0);
    load_stage(1, 32);
    cp_wait<1>();                         // stage 0 complete
    __syncthreads();

    for (int t = 0; t < T; t++) {
        if (t + 2 < T) load_stage((t + 2) % 3, (t + 2) * 32);
        compute(t % 3);
        if (t + 1 < T) {
            if (t + 2 < T) cp_wait<1>(); else cp_wait<0>();
            __syncthreads();
        }
    }

    // Epilogue
    #pragma unroll
    for (int mt = 0; mt < 4; mt++) {
        #pragma unroll
        for (int nt = 0; nt < 4; nt++) {
            #pragma unroll
            for (int half = 0; half < 2; half++) {
                int row = brow * 128 + m_base + mt * 16 + g + half * 8;
                int col = bcol * 128 + n_base + nt * 8 + 2 * tg;
                float v0 = acc[mt][nt][2 * half + 0] + bias[col];
                float v1 = acc[mt][nt][2 * half + 1] + bias[col + 1];
                if (MODE == 0) {
                    #pragma unroll
                    for (int e = 0; e < 2; e++) {
                        int cc2 = col + e;
                        float v = e ? v1 : v0;
                        int t2  = cc2 / CC;
                        int rem = cc2 - t2 * CC;
                        int h   = rem >> 6;
                        int d   = rem & 63;
                        int bI  = row >> 11;
                        int n   = row & 2047;
                        size_t idx = (((size_t)bI * HH + h) * NN + n) * DD + d;
                        if (t2 == 0)      g_Q[idx] = f2tff(v) * 0.125f;  // exact pow2
                        else if (t2 == 1) g_K[idx] = f2tff(v);
                        else              g_V[idx] = f2tff(v);
                    }
                } else {
                    float2 o; o.x = v0; o.y = v1;   // final output: no rounding
                    *(float2*)(Cout + (size_t)row * Nw + col) = o;
                }
            }
        }
    }
}

// ---------------------------------------------------------------------------
// Flash attention v4: Q frags in regs; split cp.async groups so S-mma starts
// as soon as K lands (V + alibi stream in under the S-phase mmas).
// smem 53248 B -> 3 CTAs/SM. Inputs g_Q/g_K/g_V already tf32-rounded.
// ---------------------------------------------------------------------------
__global__ __launch_bounds__(128, 3) void attn_mma_kernel(
    const float* __restrict__ alibi, const int* __restrict__ mask)
{
    extern __shared__ uint32_t smem[];
    uint32_t* Ks = smem;                        // [64][68]
    uint32_t* Vs = smem + 64 * 68;              // [64][72]
    uint32_t* Ps = smem + 64 * 68 + 64 * 72;    // [64][68]  (alibi, then P)

    const int b = blockIdx.z, h = blockIdx.y;
    const int q0 = blockIdx.x * 64;
    const int tid = threadIdx.x;
    const int warp = tid >> 5, lane = tid & 31;
    const int g = lane >> 2, tg = lane & 3;
    const int m0w = warp * 16;

    size_t bh = (size_t)b * HH + h;
    const float* Qg = g_Q + (bh * NN + q0) * DD;
    const float* Kg = g_K + bh * NN * DD;
    const float* Vg = g_V + bh * NN * DD;
    const float* alibi_bh = alibi + (bh * NN + q0) * (size_t)NN;
    const int* mask_b = mask + (size_t)b * NN;

    // Prologue: stage Q (already tf32) through Ks via cp.async
    #pragma unroll
    for (int it = 0; it < 8; it++) {
        int i = tid + it * 128;
        int r = i >> 4, c4 = (i & 15) << 2;
        cp16(s2u(&Ks[r * 68 + c4]), Qg + (size_t)r * DD + c4);
    }
    cp_commit(); cp_wait<0>();
    __syncthreads();
    uint32_t qf[8][4];
    #pragma unroll
    for (int kk = 0; kk < 8; kk++) {
        const int ak = kk * 8;
        qf[kk][0] = Ks[(m0w + g)     * 68 + ak + tg];
        qf[kk][1] = Ks[(m0w + g + 8) * 68 + ak + tg];
        qf[kk][2] = Ks[(m0w + g)     * 68 + ak + tg + 4];
        qf[kk][3] = Ks[(m0w + g + 8) * 68 + ak + tg + 4];
    }

    float oacc[8][4];
    #pragma unroll
    for (int nb = 0; nb < 8; nb++)
        #pragma unroll
        for (int c = 0; c < 4; c++) oacc[nb][c] = 0.f;

    float mi0 = -1e30f, mi1 = -1e30f, li0 = 0.f, li1 = 0.f;

    for (int kt = 0; kt < NN / 64; kt++) {
        const int m0 = kt * 64;
        __syncthreads();   // Q-frag reads done (iter 0) / prior tile consumed

        // Group 1: K tile only
        #pragma unroll
        for (int it = 0; it < 8; it++) {
            int i = tid + it * 128;
            int r = i >> 4, c4 = (i & 15) << 2;
            cp16(s2u(&Ks[r * 68 + c4]), Kg + (size_t)(m0 + r) * DD + c4);
        }
        cp_commit();
        // Group 2: V + alibi (alibi parked in Ps)
        #pragma unroll
        for (int it = 0; it < 8; it++) {
            int i = tid + it * 128;
            int r = i >> 4, c4 = (i & 15) << 2;
            cp16(s2u(&Vs[r * 72 + c4]), Vg + (size_t)(m0 + r) * DD + c4);
            cp16(s2u(&Ps[r * 68 + c4]), alibi_bh + (size_t)r * NN + m0 + c4);
        }
        cp_commit();

        cp_wait<1>();      // K complete (this thread); barrier -> all threads
        __syncthreads();

        // --- S = Q K^T (Q from registers); V+alibi still streaming ---
        float sacc[8][4];
        #pragma unroll
        for (int nb = 0; nb < 8; nb++)
            #pragma unroll
            for (int c = 0; c < 4; c++) sacc[nb][c] = 0.f;

        #pragma unroll
        for (int kk = 0; kk < 8; kk++) {
            const int ak = kk * 8;
            #pragma unroll
            for (int nb = 0; nb < 8; nb++) {
                uint32_t bf[2];
                bf[0] = Ks[(nb * 8 + g) * 68 + ak + tg];
                bf[1] = Ks[(nb * 8 + g) * 68 + ak + tg + 4];
                mma_tf32(sacc[nb], qf[kk], bf);
            }
        }

        cp_wait<0>();      // V + alibi complete
        __syncthreads();

        // --- alibi (from smem) + mask, tile max ---
        float tm0 = -1e30f, tm1 = -1e30f;
        #pragma unroll
        for (int nb = 0; nb < 8; nb++) {
            int cl = nb * 8 + 2 * tg;
            float2 al0 = *(const float2*)&Ps[(m0w + g)     * 68 + cl];
            float2 al1 = *(const float2*)&Ps[(m0w + g + 8) * 68 + cl];
            int2 mk = *(const int2*)(mask_b + m0 + cl);
            sacc[nb][0] = mk.x ? -1e30f : sacc[nb][0] + al0.x;
            sacc[nb][1] = mk.y ? -1e30f : sacc[nb][1] + al0.y;
            sacc[nb][2] = mk.x ? -1e30f : sacc[nb][2] + al1.x;
            sacc[nb][3] = mk.y ? -1e30f : sacc[nb][3] + al1.y;
            tm0 = fmaxf(tm0, fmaxf(sacc[nb][0], sacc[nb][1]));
            tm1 = fmaxf(tm1, fmaxf(sacc[nb][2], sacc[nb][3]));
        }
        tm0 = fmaxf(tm0, __shfl_xor_sync(0xffffffffu, tm0, 1));
        tm0 = fmaxf(tm0, __shfl_xor_sync(0xffffffffu, tm0, 2));
        tm1 = fmaxf(tm1, __shfl_xor_sync(0xffffffffu, tm1, 1));
        tm1 = fmaxf(tm1, __shfl_xor_sync(0xffffffffu, tm1, 2));

        // --- online softmax (P overwrites alibi slots, same thread) ---
        float mn0 = fmaxf(mi0, tm0), mn1 = fmaxf(mi1, tm1);
        float a0 = __expf(mi0 - mn0), a1 = __expf(mi1 - mn1);
        float sum0 = 0.f, sum1 = 0.f;
        #pragma unroll
        for (int nb = 0; nb < 8; nb++) {
            float p00 = __expf(sacc[nb][0] - mn0);
            float p01 = __expf(sacc[nb][1] - mn0);
            float p10 = __expf(sacc[nb][2] - mn1);
            float p11 = __expf(sacc[nb][3] - mn1);
            sum0 += p00 + p01;
            sum1 += p10 + p11;
            uint2 w0; w0.x = f2tf(p00); w0.y = f2tf(p01);
            *(uint2*)&Ps[(m0w + g) * 68 + nb * 8 + 2 * tg] = w0;
            uint2 w1; w1.x = f2tf(p10); w1.y = f2tf(p11);
            *(uint2*)&Ps[(m0w + g + 8) * 68 + nb * 8 + 2 * tg] = w1;
            oacc[nb][0] *= a0; oacc[nb][1] *= a0;
            oacc[nb][2] *= a1; oacc[nb][3] *= a1;
        }
        sum0 += __shfl_xor_sync(0xffffffffu, sum0, 1);
        sum0 += __shfl_xor_sync(0xffffffffu, sum0, 2);
        sum1 += __shfl_xor_sync(0xffffffffu, sum1, 1);
        sum1 += __shfl_xor_sync(0xffffffffu, sum1, 2);
        li0 = li0 * a0 + sum0;
        li1 = li1 * a1 + sum1;
        mi0 = mn0; mi1 = mn1;
        __syncwarp();   // P visible to own warp's A-frag loads

        // --- O += P V ---
        #pragma unroll
        for (int kk = 0; kk < 8; kk++) {
            const int kp = kk * 8;
            uint32_t a[4];
            a[0] = Ps[(m0w + g)     * 68 + kp + tg];
            a[1] = Ps[(m0w + g + 8) * 68 + kp + tg];
            a[2] = Ps[(m0w + g)     * 68 + kp + tg + 4];
            a[3] = Ps[(m0w + g + 8) * 68 + kp + tg + 4];
            #pragma unroll
            for (int nb = 0; nb < 8; nb++) {
                uint32_t bf[2];
                bf[0] = Vs[(kp + tg)     * 72 + nb * 8 + g];
                bf[1] = Vs[(kp + tg + 4) * 72 + nb * 8 + g];
                mma_tf32(oacc[nb], a, bf);
            }
        }
    }

    // Epilogue: normalize, round for proj-GEMM consumption, write [B,N,C]
    float inv0 = 1.f / li0, inv1 = 1.f / li1;
    float* O0 = g_O + ((size_t)b * NN + q0 + m0w + g) * CC + h * DD;
    float* O1 = O0 + 8 * (size_t)CC;
    #pragma unroll
    for (int nb = 0; nb < 8; nb++) {
        float2 o0;
        o0.x = f2tff(oacc[nb][0] * inv0);
        o0.y = f2tff(oacc[nb][1] * inv0);
        *(float2*)(O0 + nb * 8 + 2 * tg) = o0;
        float2 o1;
        o1.x = f2tff(oacc[nb][2] * inv1);
        o1.y = f2tff(oacc[nb][3] * inv1);
        *(float2*)(O1 + nb * 8 + 2 * tg) = o1;
    }
}

// ---------------------------------------------------------------------------
extern "C" void kernel_launch(void* const* d_in, const int* in_sizes, int n_in,
                              void* d_out, int out_size)
{
    const float* x      = (const float*)d_in[0];
    const int*   pmask  = (const int*)d_in[1];
    const float* alibi  = (const float*)d_in[2];
    const float* qkv_w  = (const float*)d_in[3];
    const float* qkv_b  = (const float*)d_in[4];
    const float* proj_w = (const float*)d_in[5];
    const float* proj_b = (const float*)d_in[6];
    float*       out    = (float*)d_out;

    float* gx; cudaGetSymbolAddress((void**)&gx, g_X);
    float* gwq; cudaGetSymbolAddress((void**)&gwq, g_Wq);
    float* gwp; cudaGetSymbolAddress((void**)&gwp, g_Wp);

    // 0) Pre-round inputs to tf32 (RNA) once per launch
    {
        int n4x = (BB * NN * CC) / 4;
        int n4q = (CC * 3 * CC) / 4;
        int n4p = (CC * CC) / 4;
        round_copy_kernel<<<(n4x + 255) / 256, 256>>>(x, gx, n4x);
        round_copy_kernel<<<(n4q + 255) / 256, 256>>>(qkv_w, gwq, n4q);
        round_copy_kernel<<<(n4p + 255) / 256, 256>>>(proj_w, gwp, n4p);
    }

    const int gemm_smem = 3 * GSTAGE * 4;        // 107520 B
    cudaFuncSetAttribute(mma_gemm_kernel<0>,
                         cudaFuncAttributeMaxDynamicSharedMemorySize, gemm_smem);
    cudaFuncSetAttribute(mma_gemm_kernel<1>,
                         cudaFuncAttributeMaxDynamicSharedMemorySize, gemm_smem);

    // 1) QKV projection (3-stage pipelined tf32 mma)
    mma_gemm_kernel<0><<<dim3(2304 / 128, (BB * NN) / 128), 256, gemm_smem>>>(
        gx, gwq, qkv_b, nullptr, CC, 3 * CC);

    // 2) Flash attention (split-group cp.async, 3 CTAs/SM)
    const int attn_smem = (64 * 68 + 64 * 72 + 64 * 68) * 4;  // 53248 B
    cudaFuncSetAttribute(attn_mma_kernel,
                         cudaFuncAttributeMaxDynamicSharedMemorySize, attn_smem);
    attn_mma_kernel<<<dim3(NN / 64, HH, BB), 128, attn_smem>>>(alibi, pmask);

    // 3) Output projection
    mma_gemm_kernel<1><<<dim3(CC / 128, (BB * NN) / 128), 256, gemm_smem>>>(
        nullptr, gwp, proj_b, out, CC, CC);
}